// round 2
// baseline (speedup 1.0000x reference)
#include <cuda_runtime.h>
#include <cstdint>
#include <cstddef>

// ---------------------------------------------------------------------------
// Problem constants
//   x:      (B=8, F=16, P=196, D=768)  -> flat (M=25088, 768)
//   w_qkv:  (2304, 768)   qkv[m,e] = dot(x[m,:], w_qkv[e,:])
//   heads H=12, hd=64; heads 0..5 spatial (chunks of 196 rows),
//   heads 6..11 temporal (chunks of 16 rows) -- both are contiguous-row
//   chunks of the flat (B, H2, N, hd) buffers because the reference uses raw
//   reshapes.
// ---------------------------------------------------------------------------

#define Bdim  8
#define Fdim  16
#define Pdim  196
#define Ddim  768
#define Hh    12
#define HD    64
#define Ndim  3136              // F*P
#define Mrows 25088             // B*N
#define E3    2304              // 3*D

#define QKV_ELEMS  ((size_t)Mrows * E3)          // 57,802,752
#define HEAD_ELEMS ((size_t)Bdim * Hh * Ndim * HD) // 19,267,584

// Scratch (allocation-free rule: __device__ globals)
__device__ float g_qkv[QKV_ELEMS];
__device__ float g_q[HEAD_ELEMS];
__device__ float g_k[HEAD_ELEMS];
__device__ float g_v[HEAD_ELEMS];
__device__ float g_w[HEAD_ELEMS];
__device__ float g_wf[(size_t)Mrows * Ddim];

// ---------------------------------------------------------------------------
// GEMM: C[M,N] = A[M,K] * B[N,K]^T (+bias). Both operands K-contiguous (NT).
// 128x128 tile, BK=16, 256 threads, 8x8 microtile per thread.
// Assumes M%128==0, N%128==0, K%16==0 (true for both calls).
// ---------------------------------------------------------------------------
__global__ __launch_bounds__(256) void gemm_nt(
    const float* __restrict__ A, const float* __restrict__ Bm,
    const float* __restrict__ bias, float* __restrict__ C,
    int Md, int Nd, int Kd)
{
    __shared__ float As[16][132];
    __shared__ float Bs[16][132];

    const int bm = blockIdx.y * 128;
    const int bn = blockIdx.x * 128;
    const int tid = threadIdx.x;

    const int lr = tid >> 2;          // 0..63
    const int lc = (tid & 3) * 4;     // 0,4,8,12

    const int tm = (tid >> 4) * 8;    // 0..120
    const int tn = (tid & 15) * 8;    // 0..120

    float acc[8][8];
#pragma unroll
    for (int i = 0; i < 8; i++)
#pragma unroll
        for (int j = 0; j < 8; j++) acc[i][j] = 0.f;

    for (int k0 = 0; k0 < Kd; k0 += 16) {
#pragma unroll
        for (int r = 0; r < 2; r++) {
            int row = lr + r * 64;
            float4 va = *(const float4*)(A + (size_t)(bm + row) * Kd + k0 + lc);
            As[lc + 0][row] = va.x; As[lc + 1][row] = va.y;
            As[lc + 2][row] = va.z; As[lc + 3][row] = va.w;
            float4 vb = *(const float4*)(Bm + (size_t)(bn + row) * Kd + k0 + lc);
            Bs[lc + 0][row] = vb.x; Bs[lc + 1][row] = vb.y;
            Bs[lc + 2][row] = vb.z; Bs[lc + 3][row] = vb.w;
        }
        __syncthreads();

#pragma unroll
        for (int k = 0; k < 16; k++) {
            float a[8], b[8];
#pragma unroll
            for (int i = 0; i < 8; i++) a[i] = As[k][tm + i];
#pragma unroll
            for (int j = 0; j < 8; j++) b[j] = Bs[k][tn + j];
#pragma unroll
            for (int i = 0; i < 8; i++)
#pragma unroll
                for (int j = 0; j < 8; j++) acc[i][j] += a[i] * b[j];
        }
        __syncthreads();
    }

    const int gm = bm + tm, gn = bn + tn;
#pragma unroll
    for (int i = 0; i < 8; i++) {
#pragma unroll
        for (int j = 0; j < 8; j++) {
            float v = acc[i][j];
            if (bias) v += bias[gn + j];
            C[(size_t)(gm + i) * Nd + gn + j] = v;
        }
    }
}

// ---------------------------------------------------------------------------
// Scatter qkv[m, t*768 + h*64 + d] -> g_{q,k,v}[((b*12+h)*N + n)*64 + d]
// ---------------------------------------------------------------------------
__global__ void scatter_qkv_k()
{
    size_t idx = (size_t)blockIdx.x * 256 + threadIdx.x;
    if (idx >= 3 * HEAD_ELEMS) return;
    int t = (int)(idx / HEAD_ELEMS);
    size_t r = idx - (size_t)t * HEAD_ELEMS;
    int bh = (int)(r / ((size_t)Ndim * HD));
    int nd = (int)(r % ((size_t)Ndim * HD));
    int n = nd >> 6, d3 = nd & 63;
    int b = bh / Hh, h = bh % Hh;
    float vv = g_qkv[((size_t)(b * Ndim + n)) * E3 + t * Ddim + h * HD + d3];
    if (t == 0)      g_q[r] = vv;
    else if (t == 1) g_k[r] = vv;
    else             g_v[r] = vv;
}

// ---------------------------------------------------------------------------
// Spatial attention: 768 groups of 196 consecutive rows (heads 0..5).
// One block per group; thread i owns query row i; flash-style online softmax
// over K/V streamed through shared memory in chunks of 64 rows.
// ---------------------------------------------------------------------------
__global__ __launch_bounds__(256) void attn_spatial_k()
{
    __shared__ float Ks[64][64];
    __shared__ float Vs[64][64];

    const int g = blockIdx.x;            // 0..767
    const int b = g / 96;
    const int h = (g % 96) / 16;         // 0..5
    const int f = g % 16;
    const size_t base = (((size_t)(b * Hh + h)) * Ndim + f * Pdim) * HD;

    const int tid = threadIdx.x;
    const bool active = tid < Pdim;

    float qr[64], acc[64];
    float mx = -1e30f, lsum = 0.f;
    if (active) {
#pragma unroll
        for (int d = 0; d < 64; d++) qr[d] = g_q[base + (size_t)tid * HD + d];
#pragma unroll
        for (int d = 0; d < 64; d++) acc[d] = 0.f;
    }

    const float scale = 0.125f;   // 1/sqrt(64)

    for (int j0 = 0; j0 < Pdim; j0 += 64) {
        int cnt = Pdim - j0; if (cnt > 64) cnt = 64;
        __syncthreads();
        for (int t = tid; t < cnt * 64; t += 256) {
            Ks[t >> 6][t & 63] = g_k[base + (size_t)j0 * HD + t];
            Vs[t >> 6][t & 63] = g_v[base + (size_t)j0 * HD + t];
        }
        __syncthreads();
        if (active) {
            for (int j = 0; j < cnt; j++) {
                float s = 0.f;
#pragma unroll
                for (int d = 0; d < 64; d++) s += qr[d] * Ks[j][d];
                s *= scale;
                if (s <= mx) {
                    float p = __expf(s - mx);
                    lsum += p;
#pragma unroll
                    for (int d = 0; d < 64; d++) acc[d] += p * Vs[j][d];
                } else {
                    float corr = __expf(mx - s);
                    lsum = lsum * corr + 1.f;
#pragma unroll
                    for (int d = 0; d < 64; d++) acc[d] = acc[d] * corr + Vs[j][d];
                    mx = s;
                }
            }
        }
    }

    if (active) {
        float inv = 1.f / lsum;
#pragma unroll
        for (int d = 0; d < 64; d++) g_w[base + (size_t)tid * HD + d] = acc[d] * inv;
    }
}

// ---------------------------------------------------------------------------
// Temporal attention: heads 6..11, groups of 16 consecutive rows (16-aligned
// chunks of n). One thread per output row; full softmax in registers.
// ---------------------------------------------------------------------------
__global__ __launch_bounds__(128) void attn_temporal_k()
{
    int tid = blockIdx.x * 128 + threadIdx.x;
    const int TOT = Bdim * 6 * Ndim;     // 150528
    if (tid >= TOT) return;
    int b = tid / (6 * Ndim);
    int rr = tid - b * (6 * Ndim);
    int h = 6 + rr / Ndim;
    int n = rr % Ndim;
    int n0 = n & ~15;
    size_t row = (((size_t)(b * Hh + h)) * Ndim + n) * HD;
    size_t gb  = (((size_t)(b * Hh + h)) * Ndim + n0) * HD;

    float qr[64];
#pragma unroll
    for (int d = 0; d < 64; d++) qr[d] = g_q[row + d];

    float s[16];
    float mx = -1e30f;
#pragma unroll
    for (int f = 0; f < 16; f++) {
        float a = 0.f;
#pragma unroll
        for (int d = 0; d < 64; d++) a += qr[d] * g_k[gb + f * HD + d];
        s[f] = a * 0.125f;
        mx = fmaxf(mx, s[f]);
    }
    float lsum = 0.f;
#pragma unroll
    for (int f = 0; f < 16; f++) { s[f] = __expf(s[f] - mx); lsum += s[f]; }
    float inv = 1.f / lsum;
#pragma unroll
    for (int f = 0; f < 16; f++) s[f] *= inv;

#pragma unroll
    for (int d = 0; d < 64; d++) {
        float a = 0.f;
#pragma unroll
        for (int f = 0; f < 16; f++) a += s[f] * g_v[gb + f * HD + d];
        g_w[row + d] = a;
    }
}

// ---------------------------------------------------------------------------
// Gather heads: g_wf[(b*N+n)*768 + h*64+d] = g_w[((b*12+h)*N+n)*64+d]
// ---------------------------------------------------------------------------
__global__ void gather_w_k()
{
    size_t idx = (size_t)blockIdx.x * 256 + threadIdx.x;
    if (idx >= HEAD_ELEMS) return;
    int e = (int)(idx % Ddim);
    size_t bn = idx / Ddim;
    int h = e >> 6, d3 = e & 63;
    int b = (int)(bn / Ndim);
    int n = (int)(bn % Ndim);
    g_wf[idx] = g_w[(((size_t)(b * Hh + h)) * Ndim + n) * HD + d3];
}

// ---------------------------------------------------------------------------
// Launch
// ---------------------------------------------------------------------------
extern "C" void kernel_launch(void* const* d_in, const int* in_sizes, int n_in,
                              void* d_out, int out_size)
{
    const float* x      = (const float*)d_in[0];
    const float* w_qkv  = (const float*)d_in[1];
    const float* w_proj = (const float*)d_in[2];
    const float* b_proj = (const float*)d_in[3];
    float* out = (float*)d_out;

    float *p_qkv, *p_wf;
    cudaGetSymbolAddress((void**)&p_qkv, g_qkv);
    cudaGetSymbolAddress((void**)&p_wf,  g_wf);

    // 1) qkv = x @ w_qkv^T   (25088 x 2304 x 768)
    gemm_nt<<<dim3(E3 / 128, Mrows / 128), 256>>>(x, w_qkv, nullptr, p_qkv,
                                                  Mrows, E3, Ddim);
    // 2) split into q/k/v in (B,12,N,64) layout
    scatter_qkv_k<<<(unsigned)((3 * HEAD_ELEMS) / 256), 256>>>();
    // 3) spatial attention (heads 0..5)
    attn_spatial_k<<<768, 256>>>();
    // 4) temporal attention (heads 6..11)
    attn_temporal_k<<<(Bdim * 6 * Ndim) / 128, 128>>>();
    // 5) interleave heads back to (M,768)
    gather_w_k<<<(unsigned)(HEAD_ELEMS / 256), 256>>>();
    // 6) out = w @ w_proj^T + b_proj   (25088 x 768 x 768)
    gemm_nt<<<dim3(Ddim / 128, Mrows / 128), 256>>>(p_wf, w_proj, b_proj, out,
                                                    Mrows, Ddim, Ddim);
}

// round 4
// speedup vs baseline: 1.6428x; 1.6428x over previous
#include <cuda_runtime.h>
#include <cuda_bf16.h>
#include <cstdint>
#include <cstddef>

// ---------------------------------------------------------------------------
// Problem constants
// ---------------------------------------------------------------------------
#define Bdim  8
#define Fdim  16
#define Pdim  196
#define Ddim  768
#define Hh    12
#define HD    64
#define Ndim  3136              // F*P
#define Mrows 25088             // B*N
#define E3    2304              // 3*D

#define QKV_ELEMS  ((size_t)Mrows * E3)
#define HEAD_ELEMS ((size_t)Bdim * Hh * Ndim * HD)
#define MD_ELEMS   ((size_t)Mrows * Ddim)

// Scratch (__device__ globals; allocation-free rule)
__device__ float g_qkv[QKV_ELEMS];
__device__ float g_q[HEAD_ELEMS];
__device__ float g_k[HEAD_ELEMS];
__device__ float g_v[HEAD_ELEMS];
__device__ float g_w[HEAD_ELEMS];

__device__ __nv_bfloat16 g_xhi[MD_ELEMS];
__device__ __nv_bfloat16 g_xlo[MD_ELEMS];
__device__ __nv_bfloat16 g_wqkv_hi[(size_t)E3 * Ddim];
__device__ __nv_bfloat16 g_wqkv_lo[(size_t)E3 * Ddim];
__device__ __nv_bfloat16 g_wproj_hi[(size_t)Ddim * Ddim];
__device__ __nv_bfloat16 g_wproj_lo[(size_t)Ddim * Ddim];
__device__ __nv_bfloat16 g_wf_hi[MD_ELEMS];
__device__ __nv_bfloat16 g_wf_lo[MD_ELEMS];

// ---------------------------------------------------------------------------
// helpers
// ---------------------------------------------------------------------------
__device__ __forceinline__ void cp_async16(uint32_t dst, const void* src) {
    asm volatile("cp.async.cg.shared.global [%0], [%1], 16;"
                 :: "r"(dst), "l"(src) : "memory");
}
#define CP_COMMIT() asm volatile("cp.async.commit_group;" ::: "memory")
template <int N> __device__ __forceinline__ void cp_wait() {
    asm volatile("cp.async.wait_group %0;" :: "n"(N) : "memory");
}
__device__ __forceinline__ uint32_t smem_u32(const void* p) {
    uint32_t a;
    asm("{ .reg .u64 t; cvta.to.shared.u64 t, %1; cvt.u32.u64 %0, t; }"
        : "=r"(a) : "l"(p));
    return a;
}

__device__ __forceinline__ void mma16816(float* d,
                                         uint32_t a0, uint32_t a1, uint32_t a2, uint32_t a3,
                                         uint32_t b0, uint32_t b1) {
    asm volatile(
        "mma.sync.aligned.m16n8k16.row.col.f32.bf16.bf16.f32 "
        "{%0,%1,%2,%3}, {%4,%5,%6,%7}, {%8,%9}, {%0,%1,%2,%3};"
        : "+f"(d[0]), "+f"(d[1]), "+f"(d[2]), "+f"(d[3])
        : "r"(a0), "r"(a1), "r"(a2), "r"(a3), "r"(b0), "r"(b1));
}

// ---------------------------------------------------------------------------
// HMMA GEMM:  C[M,N] = (Ahi+Alo)[M,768] * (Bhi+Blo)[N,768]^T (+bias)
// 128x128x32 CTA tile, 256 threads, warp grid 2(M)x4(N), warp tile 64x32.
// bf16 split (hi*hi + hi*lo + lo*hi), fp32 accumulate.
// ---------------------------------------------------------------------------
#define BK       32
#define LDK      40                       // padded row length (bf16)
#define TILE_B   (128 * LDK * 2)          // 10240 bytes per matrix tile
#define STAGE_B  (4 * TILE_B)             // Ahi, Alo, Bhi, Blo = 40960
#define NSTAGE   3
#define GSMEM    (NSTAGE * STAGE_B)       // 122880
#define OFF_AHI  0
#define OFF_ALO  TILE_B
#define OFF_BHI  (2 * TILE_B)
#define OFF_BLO  (3 * TILE_B)

__global__ __launch_bounds__(256, 1) void tgemm_k(
    const __nv_bfloat16* __restrict__ Ahi, const __nv_bfloat16* __restrict__ Alo,
    const __nv_bfloat16* __restrict__ Bhi, const __nv_bfloat16* __restrict__ Blo,
    const float* __restrict__ bias, float* __restrict__ C, int Nd)
{
    extern __shared__ char smem[];
    const uint32_t sb = smem_u32(smem);

    const int tid  = threadIdx.x;
    const int lane = tid & 31;
    const int wid  = tid >> 5;
    const int wm   = wid & 1;          // 0..1 : M
    const int wn   = wid >> 1;         // 0..3 : N
    const int g    = lane >> 2;        // 0..7
    const int tg   = lane & 3;         // 0..3

    const int bm = blockIdx.y * 128;
    const int bn = blockIdx.x * 128;

    // gmem->smem loader role: 4 tiles x 64 threads, 8 granules (16B) each
    const int tile = tid >> 6;         // 0:Ahi 1:Alo 2:Bhi 3:Blo
    const int lt   = tid & 63;
    const __nv_bfloat16* src_base =
        (tile == 0) ? Ahi : (tile == 1) ? Alo : (tile == 2) ? Bhi : Blo;
    const int rowbase = (tile < 2) ? bm : bn;
    const uint32_t tile_off = tile * TILE_B;

    auto load_chunk = [&](int k0, int stage) {
        const uint32_t dbase = sb + stage * STAGE_B + tile_off;
#pragma unroll
        for (int j = 0; j < 8; j++) {
            int id  = lt + j * 64;          // 0..511
            int row = id >> 2;              // 0..127
            int gr  = id & 3;               // 16B granule within 64B row
            const void* src = src_base + (size_t)(rowbase + row) * Ddim + k0 + gr * 8;
            cp_async16(dbase + (uint32_t)(row * (LDK * 2) + gr * 16), src);
        }
        CP_COMMIT();
    };

    float acc[4][4][4];
#pragma unroll
    for (int i = 0; i < 4; i++)
#pragma unroll
        for (int j = 0; j < 4; j++)
#pragma unroll
            for (int q = 0; q < 4; q++) acc[i][j][q] = 0.f;

    load_chunk(0, 0);
    load_chunk(BK, 1);

    const int NCH = Ddim / BK;   // 24
    for (int c = 0; c < NCH; c++) {
        if (c + 1 < NCH) cp_wait<1>(); else cp_wait<0>();
        __syncthreads();
        if (c + 2 < NCH) load_chunk((c + 2) * BK, (c + 2) % NSTAGE);

        const char* st = smem + (c % NSTAGE) * STAGE_B;
        const char* pAhi = st + OFF_AHI;
        const char* pAlo = st + OFF_ALO;
        const char* pBhi = st + OFF_BHI;
        const char* pBlo = st + OFF_BLO;

#pragma unroll
        for (int ks = 0; ks < BK / 16; ks++) {
            const int kc = ks * 16 + tg * 2;     // bf16 col of first element
            uint32_t ah[4][4], al[4][4];
#pragma unroll
            for (int mt = 0; mt < 4; mt++) {
                int r0 = wm * 64 + mt * 16 + g;
                int o00 = (r0 * LDK + kc) * 2;
                int o10 = ((r0 + 8) * LDK + kc) * 2;
                ah[mt][0] = *(const uint32_t*)(pAhi + o00);
                ah[mt][1] = *(const uint32_t*)(pAhi + o10);
                ah[mt][2] = *(const uint32_t*)(pAhi + o00 + 16);
                ah[mt][3] = *(const uint32_t*)(pAhi + o10 + 16);
                al[mt][0] = *(const uint32_t*)(pAlo + o00);
                al[mt][1] = *(const uint32_t*)(pAlo + o10);
                al[mt][2] = *(const uint32_t*)(pAlo + o00 + 16);
                al[mt][3] = *(const uint32_t*)(pAlo + o10 + 16);
            }
#pragma unroll
            for (int nt = 0; nt < 4; nt++) {
                int rb = wn * 32 + nt * 8 + g;
                int ob = (rb * LDK + kc) * 2;
                uint32_t bh0 = *(const uint32_t*)(pBhi + ob);
                uint32_t bh1 = *(const uint32_t*)(pBhi + ob + 16);
                uint32_t bl0 = *(const uint32_t*)(pBlo + ob);
                uint32_t bl1 = *(const uint32_t*)(pBlo + ob + 16);
#pragma unroll
                for (int mt = 0; mt < 4; mt++) {
                    mma16816(acc[mt][nt], ah[mt][0], ah[mt][1], ah[mt][2], ah[mt][3], bh0, bh1);
                    mma16816(acc[mt][nt], ah[mt][0], ah[mt][1], ah[mt][2], ah[mt][3], bl0, bl1);
                    mma16816(acc[mt][nt], al[mt][0], al[mt][1], al[mt][2], al[mt][3], bh0, bh1);
                }
            }
        }
        __syncthreads();
    }

    // epilogue
#pragma unroll
    for (int mt = 0; mt < 4; mt++) {
        int r0 = bm + wm * 64 + mt * 16 + g;
#pragma unroll
        for (int nt = 0; nt < 4; nt++) {
            int c0 = bn + wn * 32 + nt * 8 + tg * 2;
            float b0 = 0.f, b1 = 0.f;
            if (bias) { b0 = bias[c0]; b1 = bias[c0 + 1]; }
            float2 v0 = make_float2(acc[mt][nt][0] + b0, acc[mt][nt][1] + b1);
            float2 v1 = make_float2(acc[mt][nt][2] + b0, acc[mt][nt][3] + b1);
            *(float2*)(C + (size_t)r0 * Nd + c0) = v0;
            *(float2*)(C + (size_t)(r0 + 8) * Nd + c0) = v1;
        }
    }
}

// ---------------------------------------------------------------------------
// fp32 -> bf16 hi/lo split
// ---------------------------------------------------------------------------
__global__ void cvt_split_k(const float* __restrict__ in,
                            __nv_bfloat16* __restrict__ hi,
                            __nv_bfloat16* __restrict__ lo, size_t n)
{
    size_t i = (size_t)blockIdx.x * 256 + threadIdx.x;
    if (i >= n) return;
    float v = in[i];
    __nv_bfloat16 h = __float2bfloat16(v);
    hi[i] = h;
    lo[i] = __float2bfloat16(v - __bfloat162float(h));
}

// ---------------------------------------------------------------------------
// Scatter qkv -> q/k/v in (B,12,N,64)
// ---------------------------------------------------------------------------
__global__ void scatter_qkv_k()
{
    size_t idx = (size_t)blockIdx.x * 256 + threadIdx.x;
    if (idx >= 3 * HEAD_ELEMS) return;
    int t = (int)(idx / HEAD_ELEMS);
    size_t r = idx - (size_t)t * HEAD_ELEMS;
    int bh = (int)(r / ((size_t)Ndim * HD));
    int nd = (int)(r % ((size_t)Ndim * HD));
    int n = nd >> 6, d3 = nd & 63;
    int b = bh / Hh, h = bh % Hh;
    float vv = g_qkv[((size_t)(b * Ndim + n)) * E3 + t * Ddim + h * HD + d3];
    if (t == 0)      g_q[r] = vv;
    else if (t == 1) g_k[r] = vv;
    else             g_v[r] = vv;
}

// ---------------------------------------------------------------------------
// Spatial attention: 768 groups of 196 rows (heads 0..5)
// ---------------------------------------------------------------------------
__global__ __launch_bounds__(256) void attn_spatial_k()
{
    __shared__ float Ks[64][64];
    __shared__ float Vs[64][64];

    const int g = blockIdx.x;
    const int b = g / 96;
    const int h = (g % 96) / 16;
    const int f = g % 16;
    const size_t base = (((size_t)(b * Hh + h)) * Ndim + f * Pdim) * HD;

    const int tid = threadIdx.x;
    const bool active = tid < Pdim;

    float qr[64], acc[64];
    float mx = -1e30f, lsum = 0.f;
    if (active) {
#pragma unroll
        for (int d = 0; d < 64; d++) qr[d] = g_q[base + (size_t)tid * HD + d];
#pragma unroll
        for (int d = 0; d < 64; d++) acc[d] = 0.f;
    }

    const float scale = 0.125f;

    for (int j0 = 0; j0 < Pdim; j0 += 64) {
        int cnt = Pdim - j0; if (cnt > 64) cnt = 64;
        __syncthreads();
        for (int t = tid; t < cnt * 64; t += 256) {
            Ks[t >> 6][t & 63] = g_k[base + (size_t)j0 * HD + t];
            Vs[t >> 6][t & 63] = g_v[base + (size_t)j0 * HD + t];
        }
        __syncthreads();
        if (active) {
            for (int j = 0; j < cnt; j++) {
                float s = 0.f;
#pragma unroll
                for (int d = 0; d < 64; d++) s += qr[d] * Ks[j][d];
                s *= scale;
                if (s <= mx) {
                    float p = __expf(s - mx);
                    lsum += p;
#pragma unroll
                    for (int d = 0; d < 64; d++) acc[d] += p * Vs[j][d];
                } else {
                    float corr = __expf(mx - s);
                    lsum = lsum * corr + 1.f;
#pragma unroll
                    for (int d = 0; d < 64; d++) acc[d] = acc[d] * corr + Vs[j][d];
                    mx = s;
                }
            }
        }
    }

    if (active) {
        float inv = 1.f / lsum;
#pragma unroll
        for (int d = 0; d < 64; d++) g_w[base + (size_t)tid * HD + d] = acc[d] * inv;
    }
}

// ---------------------------------------------------------------------------
// Temporal attention: heads 6..11, groups of 16 rows
// ---------------------------------------------------------------------------
__global__ __launch_bounds__(128) void attn_temporal_k()
{
    int tid = blockIdx.x * 128 + threadIdx.x;
    const int TOT = Bdim * 6 * Ndim;
    if (tid >= TOT) return;
    int b = tid / (6 * Ndim);
    int rr = tid - b * (6 * Ndim);
    int h = 6 + rr / Ndim;
    int n = rr % Ndim;
    int n0 = n & ~15;
    size_t row = (((size_t)(b * Hh + h)) * Ndim + n) * HD;
    size_t gb  = (((size_t)(b * Hh + h)) * Ndim + n0) * HD;

    float qr[64];
#pragma unroll
    for (int d = 0; d < 64; d++) qr[d] = g_q[row + d];

    float s[16];
    float mx = -1e30f;
#pragma unroll
    for (int f = 0; f < 16; f++) {
        float a = 0.f;
#pragma unroll
        for (int d = 0; d < 64; d++) a += qr[d] * g_k[gb + f * HD + d];
        s[f] = a * 0.125f;
        mx = fmaxf(mx, s[f]);
    }
    float lsum = 0.f;
#pragma unroll
    for (int f = 0; f < 16; f++) { s[f] = __expf(s[f] - mx); lsum += s[f]; }
    float inv = 1.f / lsum;
#pragma unroll
    for (int f = 0; f < 16; f++) s[f] *= inv;

#pragma unroll
    for (int d = 0; d < 64; d++) {
        float a = 0.f;
#pragma unroll
        for (int f = 0; f < 16; f++) a += s[f] * g_v[gb + f * HD + d];
        g_w[row + d] = a;
    }
}

// ---------------------------------------------------------------------------
// Gather heads + bf16 split
// ---------------------------------------------------------------------------
__global__ void gather_w_k()
{
    size_t idx = (size_t)blockIdx.x * 256 + threadIdx.x;
    if (idx >= HEAD_ELEMS) return;
    int e = (int)(idx % Ddim);
    size_t bn = idx / Ddim;
    int h = e >> 6, d3 = e & 63;
    int b = (int)(bn / Ndim);
    int n = (int)(bn % Ndim);
    float v = g_w[(((size_t)(b * Hh + h)) * Ndim + n) * HD + d3];
    __nv_bfloat16 hi = __float2bfloat16(v);
    g_wf_hi[idx] = hi;
    g_wf_lo[idx] = __float2bfloat16(v - __bfloat162float(hi));
}

// ---------------------------------------------------------------------------
// Launch
// ---------------------------------------------------------------------------
extern "C" void kernel_launch(void* const* d_in, const int* in_sizes, int n_in,
                              void* d_out, int out_size)
{
    const float* x      = (const float*)d_in[0];
    const float* w_qkv  = (const float*)d_in[1];
    const float* w_proj = (const float*)d_in[2];
    const float* b_proj = (const float*)d_in[3];
    float* out = (float*)d_out;

    float* p_qkv;
    __nv_bfloat16 *p_xhi, *p_xlo, *p_qkvw_hi, *p_qkvw_lo;
    __nv_bfloat16 *p_projw_hi, *p_projw_lo, *p_wfhi, *p_wflo;
    cudaGetSymbolAddress((void**)&p_qkv, g_qkv);
    cudaGetSymbolAddress((void**)&p_xhi, g_xhi);
    cudaGetSymbolAddress((void**)&p_xlo, g_xlo);
    cudaGetSymbolAddress((void**)&p_qkvw_hi, g_wqkv_hi);
    cudaGetSymbolAddress((void**)&p_qkvw_lo, g_wqkv_lo);
    cudaGetSymbolAddress((void**)&p_projw_hi, g_wproj_hi);
    cudaGetSymbolAddress((void**)&p_projw_lo, g_wproj_lo);
    cudaGetSymbolAddress((void**)&p_wfhi, g_wf_hi);
    cudaGetSymbolAddress((void**)&p_wflo, g_wf_lo);

    cudaFuncSetAttribute(tgemm_k, cudaFuncAttributeMaxDynamicSharedMemorySize, GSMEM);

    // 0) bf16 splits of inputs / weights
    cvt_split_k<<<(unsigned)((MD_ELEMS + 255) / 256), 256>>>(x, p_xhi, p_xlo, MD_ELEMS);
    cvt_split_k<<<(unsigned)(((size_t)E3 * Ddim + 255) / 256), 256>>>(
        w_qkv, p_qkvw_hi, p_qkvw_lo, (size_t)E3 * Ddim);
    cvt_split_k<<<(unsigned)(((size_t)Ddim * Ddim + 255) / 256), 256>>>(
        w_proj, p_projw_hi, p_projw_lo, (size_t)Ddim * Ddim);

    // 1) qkv = x @ w_qkv^T   (25088 x 2304 x 768)
    tgemm_k<<<dim3(E3 / 128, Mrows / 128), 256, GSMEM>>>(
        p_xhi, p_xlo, p_qkvw_hi, p_qkvw_lo, nullptr, p_qkv, E3);

    // 2) split q/k/v
    scatter_qkv_k<<<(unsigned)((3 * HEAD_ELEMS) / 256), 256>>>();

    // 3) spatial attention
    attn_spatial_k<<<768, 256>>>();

    // 4) temporal attention
    attn_temporal_k<<<(Bdim * 6 * Ndim) / 128, 128>>>();

    // 5) interleave heads + bf16 split
    gather_w_k<<<(unsigned)(HEAD_ELEMS / 256), 256>>>();

    // 6) out = w @ w_proj^T + b_proj   (25088 x 768 x 768)
    tgemm_k<<<dim3(Ddim / 128, Mrows / 128), 256, GSMEM>>>(
        p_wfhi, p_wflo, p_projw_hi, p_projw_lo, b_proj, out, Ddim);
}

// round 5
// speedup vs baseline: 1.7171x; 1.0453x over previous
#include <cuda_runtime.h>
#include <cuda_bf16.h>
#include <cstdint>
#include <cstddef>

// ---------------------------------------------------------------------------
// Problem constants
// ---------------------------------------------------------------------------
#define Bdim  8
#define Fdim  16
#define Pdim  196
#define Ddim  768
#define Hh    12
#define HD    64
#define Ndim  3136              // F*P
#define Mrows 25088             // B*N
#define E3    2304              // 3*D

#define QKV_ELEMS  ((size_t)Mrows * E3)
#define HEAD_ELEMS ((size_t)Bdim * Hh * Ndim * HD)
#define MD_ELEMS   ((size_t)Mrows * Ddim)

// Scratch (__device__ globals; allocation-free rule)
__device__ float g_qkv[QKV_ELEMS];
__device__ float g_q[HEAD_ELEMS];
__device__ float g_k[HEAD_ELEMS];
__device__ float g_v[HEAD_ELEMS];
__device__ float g_w[HEAD_ELEMS];

__device__ __nv_bfloat16 g_xhi[MD_ELEMS];
__device__ __nv_bfloat16 g_xlo[MD_ELEMS];
__device__ __nv_bfloat16 g_wqkv_hi[(size_t)E3 * Ddim];
__device__ __nv_bfloat16 g_wqkv_lo[(size_t)E3 * Ddim];
__device__ __nv_bfloat16 g_wproj_hi[(size_t)Ddim * Ddim];
__device__ __nv_bfloat16 g_wproj_lo[(size_t)Ddim * Ddim];
__device__ __nv_bfloat16 g_wf_hi[MD_ELEMS];
__device__ __nv_bfloat16 g_wf_lo[MD_ELEMS];

// ---------------------------------------------------------------------------
// helpers
// ---------------------------------------------------------------------------
__device__ __forceinline__ void cp_async16(uint32_t dst, const void* src) {
    asm volatile("cp.async.cg.shared.global [%0], [%1], 16;"
                 :: "r"(dst), "l"(src) : "memory");
}
#define CP_COMMIT() asm volatile("cp.async.commit_group;" ::: "memory")
template <int N> __device__ __forceinline__ void cp_wait() {
    asm volatile("cp.async.wait_group %0;" :: "n"(N) : "memory");
}
__device__ __forceinline__ uint32_t smem_u32(const void* p) {
    uint32_t a;
    asm("{ .reg .u64 t; cvta.to.shared.u64 t, %1; cvt.u32.u64 %0, t; }"
        : "=r"(a) : "l"(p));
    return a;
}

__device__ __forceinline__ void mma16816(float* d,
                                         uint32_t a0, uint32_t a1, uint32_t a2, uint32_t a3,
                                         uint32_t b0, uint32_t b1) {
    asm volatile(
        "mma.sync.aligned.m16n8k16.row.col.f32.bf16.bf16.f32 "
        "{%0,%1,%2,%3}, {%4,%5,%6,%7}, {%8,%9}, {%0,%1,%2,%3};"
        : "+f"(d[0]), "+f"(d[1]), "+f"(d[2]), "+f"(d[3])
        : "r"(a0), "r"(a1), "r"(a2), "r"(a3), "r"(b0), "r"(b1));
}

// ---------------------------------------------------------------------------
// HMMA GEMM:  C[M,N] = (Ahi+Alo)[M,768] * (Bhi+Blo)[N,768]^T (+bias)
// 128x128x16 CTA tile, 256 threads, warp grid 2(M)x4(N), warp tile 64x32.
// bf16 split (hi*hi + hi*lo + lo*hi), fp32 accumulate.
// 4-stage cp.async pipeline; LDK=24 rows (48B) are bank-conflict-free and
// 16B aligned; 2 CTAs/SM.
// ---------------------------------------------------------------------------
#define BK       16
#define LDK      24                       // padded row length (bf16)
#define TILE_B   (128 * LDK * 2)          // 6144 bytes per matrix tile
#define STAGE_B  (4 * TILE_B)             // Ahi, Alo, Bhi, Blo = 24576
#define NSTAGE   4
#define GSMEM    (NSTAGE * STAGE_B)       // 98304
#define OFF_AHI  0
#define OFF_ALO  TILE_B
#define OFF_BHI  (2 * TILE_B)
#define OFF_BLO  (3 * TILE_B)

__global__ __launch_bounds__(256, 2) void tgemm_k(
    const __nv_bfloat16* __restrict__ Ahi, const __nv_bfloat16* __restrict__ Alo,
    const __nv_bfloat16* __restrict__ Bhi, const __nv_bfloat16* __restrict__ Blo,
    const float* __restrict__ bias, float* __restrict__ C, int Nd)
{
    extern __shared__ char smem[];
    const uint32_t sb = smem_u32(smem);

    const int tid  = threadIdx.x;
    const int lane = tid & 31;
    const int wid  = tid >> 5;
    const int wm   = wid & 1;          // 0..1 : M
    const int wn   = wid >> 1;         // 0..3 : N
    const int g    = lane >> 2;        // 0..7
    const int tg   = lane & 3;         // 0..3

    const int bm = blockIdx.y * 128;
    const int bn = blockIdx.x * 128;

    // gmem->smem loader role: 4 tiles x 64 threads, 4 granules (16B) each
    const int tile = tid >> 6;         // 0:Ahi 1:Alo 2:Bhi 3:Blo
    const int lt   = tid & 63;
    const __nv_bfloat16* src_base =
        (tile == 0) ? Ahi : (tile == 1) ? Alo : (tile == 2) ? Bhi : Blo;
    const int rowbase = (tile < 2) ? bm : bn;
    const uint32_t tile_off = tile * TILE_B;

    auto load_chunk = [&](int k0, int stage) {
        const uint32_t dbase = sb + stage * STAGE_B + tile_off;
#pragma unroll
        for (int j = 0; j < 4; j++) {
            int id  = lt + j * 64;          // 0..255
            int row = id >> 1;              // 0..127
            int gr  = id & 1;               // 16B granule within 32B row
            const void* src = src_base + (size_t)(rowbase + row) * Ddim + k0 + gr * 8;
            cp_async16(dbase + (uint32_t)(row * (LDK * 2) + gr * 16), src);
        }
        CP_COMMIT();
    };

    float acc[4][4][4];
#pragma unroll
    for (int i = 0; i < 4; i++)
#pragma unroll
        for (int j = 0; j < 4; j++)
#pragma unroll
            for (int q = 0; q < 4; q++) acc[i][j][q] = 0.f;

    load_chunk(0, 0);
    load_chunk(BK, 1);
    load_chunk(2 * BK, 2);

    const int NCH = Ddim / BK;   // 48
    for (int c = 0; c < NCH; c++) {
        if (c < NCH - 2)      cp_wait<2>();
        else if (c == NCH - 2) cp_wait<1>();
        else                   cp_wait<0>();
        __syncthreads();
        if (c + 3 < NCH) load_chunk((c + 3) * BK, (c + 3) % NSTAGE);

        const char* st = smem + (c % NSTAGE) * STAGE_B;
        const char* pAhi = st + OFF_AHI;
        const char* pAlo = st + OFF_ALO;
        const char* pBhi = st + OFF_BHI;
        const char* pBlo = st + OFF_BLO;

        const int kc = tg * 2;     // bf16 col of first element
        uint32_t ah[4][4], al[4][4];
#pragma unroll
        for (int mt = 0; mt < 4; mt++) {
            int r0 = wm * 64 + mt * 16 + g;
            int o00 = (r0 * LDK + kc) * 2;
            int o10 = ((r0 + 8) * LDK + kc) * 2;
            ah[mt][0] = *(const uint32_t*)(pAhi + o00);
            ah[mt][1] = *(const uint32_t*)(pAhi + o10);
            ah[mt][2] = *(const uint32_t*)(pAhi + o00 + 16);
            ah[mt][3] = *(const uint32_t*)(pAhi + o10 + 16);
            al[mt][0] = *(const uint32_t*)(pAlo + o00);
            al[mt][1] = *(const uint32_t*)(pAlo + o10);
            al[mt][2] = *(const uint32_t*)(pAlo + o00 + 16);
            al[mt][3] = *(const uint32_t*)(pAlo + o10 + 16);
        }
#pragma unroll
        for (int nt = 0; nt < 4; nt++) {
            int rb = wn * 32 + nt * 8 + g;
            int ob = (rb * LDK + kc) * 2;
            uint32_t bh0 = *(const uint32_t*)(pBhi + ob);
            uint32_t bh1 = *(const uint32_t*)(pBhi + ob + 16);
            uint32_t bl0 = *(const uint32_t*)(pBlo + ob);
            uint32_t bl1 = *(const uint32_t*)(pBlo + ob + 16);
#pragma unroll
            for (int mt = 0; mt < 4; mt++) {
                mma16816(acc[mt][nt], ah[mt][0], ah[mt][1], ah[mt][2], ah[mt][3], bh0, bh1);
                mma16816(acc[mt][nt], ah[mt][0], ah[mt][1], ah[mt][2], ah[mt][3], bl0, bl1);
                mma16816(acc[mt][nt], al[mt][0], al[mt][1], al[mt][2], al[mt][3], bh0, bh1);
            }
        }
        __syncthreads();
    }

    // epilogue
#pragma unroll
    for (int mt = 0; mt < 4; mt++) {
        int r0 = bm + wm * 64 + mt * 16 + g;
#pragma unroll
        for (int nt = 0; nt < 4; nt++) {
            int c0 = bn + wn * 32 + nt * 8 + tg * 2;
            float b0 = 0.f, b1 = 0.f;
            if (bias) { b0 = bias[c0]; b1 = bias[c0 + 1]; }
            float2 v0 = make_float2(acc[mt][nt][0] + b0, acc[mt][nt][1] + b1);
            float2 v1 = make_float2(acc[mt][nt][2] + b0, acc[mt][nt][3] + b1);
            *(float2*)(C + (size_t)r0 * Nd + c0) = v0;
            *(float2*)(C + (size_t)(r0 + 8) * Nd + c0) = v1;
        }
    }
}

// ---------------------------------------------------------------------------
// fp32 -> bf16 hi/lo split
// ---------------------------------------------------------------------------
__global__ void cvt_split_k(const float* __restrict__ in,
                            __nv_bfloat16* __restrict__ hi,
                            __nv_bfloat16* __restrict__ lo, size_t n)
{
    size_t i = (size_t)blockIdx.x * 256 + threadIdx.x;
    if (i >= n) return;
    float v = in[i];
    __nv_bfloat16 h = __float2bfloat16(v);
    hi[i] = h;
    lo[i] = __float2bfloat16(v - __bfloat162float(h));
}

// ---------------------------------------------------------------------------
// Scatter qkv -> q/k/v in (B,12,N,64)
// ---------------------------------------------------------------------------
__global__ void scatter_qkv_k()
{
    size_t idx = (size_t)blockIdx.x * 256 + threadIdx.x;
    if (idx >= 3 * HEAD_ELEMS) return;
    int t = (int)(idx / HEAD_ELEMS);
    size_t r = idx - (size_t)t * HEAD_ELEMS;
    int bh = (int)(r / ((size_t)Ndim * HD));
    int nd = (int)(r % ((size_t)Ndim * HD));
    int n = nd >> 6, d3 = nd & 63;
    int b = bh / Hh, h = bh % Hh;
    float vv = g_qkv[((size_t)(b * Ndim + n)) * E3 + t * Ddim + h * HD + d3];
    if (t == 0)      g_q[r] = vv;
    else if (t == 1) g_k[r] = vv;
    else             g_v[r] = vv;
}

// ---------------------------------------------------------------------------
// Spatial attention: 768 groups of 196 rows (heads 0..5), float4 version.
// ---------------------------------------------------------------------------
__global__ __launch_bounds__(256) void attn_spatial_k()
{
    __shared__ float4 K4[64][16];
    __shared__ float4 V4[64][16];

    const int g = blockIdx.x;
    const int b = g / 96;
    const int h = (g % 96) / 16;
    const int f = g % 16;
    const size_t base = (((size_t)(b * Hh + h)) * Ndim + f * Pdim) * HD;

    const int tid = threadIdx.x;
    const bool active = tid < Pdim;

    float4 q4[16], a4[16];
    float mx = -1e30f, lsum = 0.f;
    if (active) {
        const float4* qp = (const float4*)(g_q + base + (size_t)tid * HD);
#pragma unroll
        for (int i = 0; i < 16; i++) q4[i] = qp[i];
#pragma unroll
        for (int i = 0; i < 16; i++) a4[i] = make_float4(0.f, 0.f, 0.f, 0.f);
    }

    const float scale = 0.125f;

    for (int j0 = 0; j0 < Pdim; j0 += 64) {
        int cnt = Pdim - j0; if (cnt > 64) cnt = 64;
        __syncthreads();
        {
            const float4* kp = (const float4*)(g_k + base + (size_t)j0 * HD);
            const float4* vp = (const float4*)(g_v + base + (size_t)j0 * HD);
            for (int t = tid; t < cnt * 16; t += 256) {
                K4[t >> 4][t & 15] = kp[t];
                V4[t >> 4][t & 15] = vp[t];
            }
        }
        __syncthreads();
        if (active) {
            for (int j = 0; j < cnt; j++) {
                float s = 0.f;
#pragma unroll
                for (int i = 0; i < 16; i++) {
                    float4 kv = K4[j][i];
                    s = fmaf(q4[i].x, kv.x, s);
                    s = fmaf(q4[i].y, kv.y, s);
                    s = fmaf(q4[i].z, kv.z, s);
                    s = fmaf(q4[i].w, kv.w, s);
                }
                s *= scale;
                if (s <= mx) {
                    float p = __expf(s - mx);
                    lsum += p;
#pragma unroll
                    for (int i = 0; i < 16; i++) {
                        float4 vv = V4[j][i];
                        a4[i].x = fmaf(p, vv.x, a4[i].x);
                        a4[i].y = fmaf(p, vv.y, a4[i].y);
                        a4[i].z = fmaf(p, vv.z, a4[i].z);
                        a4[i].w = fmaf(p, vv.w, a4[i].w);
                    }
                } else {
                    float corr = __expf(mx - s);
                    lsum = lsum * corr + 1.f;
#pragma unroll
                    for (int i = 0; i < 16; i++) {
                        float4 vv = V4[j][i];
                        a4[i].x = fmaf(a4[i].x, corr, vv.x);
                        a4[i].y = fmaf(a4[i].y, corr, vv.y);
                        a4[i].z = fmaf(a4[i].z, corr, vv.z);
                        a4[i].w = fmaf(a4[i].w, corr, vv.w);
                    }
                    mx = s;
                }
            }
        }
    }

    if (active) {
        float inv = 1.f / lsum;
        float4* wp = (float4*)(g_w + base + (size_t)tid * HD);
#pragma unroll
        for (int i = 0; i < 16; i++) {
            float4 o;
            o.x = a4[i].x * inv; o.y = a4[i].y * inv;
            o.z = a4[i].z * inv; o.w = a4[i].w * inv;
            wp[i] = o;
        }
    }
}

// ---------------------------------------------------------------------------
// Temporal attention: heads 6..11, groups of 16 rows. float4 + chunked output.
// ---------------------------------------------------------------------------
__global__ __launch_bounds__(128) void attn_temporal_k()
{
    int tid = blockIdx.x * 128 + threadIdx.x;
    const int TOT = Bdim * 6 * Ndim;
    if (tid >= TOT) return;
    int b = tid / (6 * Ndim);
    int rr = tid - b * (6 * Ndim);
    int h = 6 + rr / Ndim;
    int n = rr % Ndim;
    int n0 = n & ~15;
    size_t row = (((size_t)(b * Hh + h)) * Ndim + n) * HD;
    size_t gb  = (((size_t)(b * Hh + h)) * Ndim + n0) * HD;

    float4 q4[16];
    const float4* qp = (const float4*)(g_q + row);
#pragma unroll
    for (int i = 0; i < 16; i++) q4[i] = qp[i];

    float s[16];
    float mx = -1e30f;
#pragma unroll
    for (int f = 0; f < 16; f++) {
        const float4* kp = (const float4*)(g_k + gb + (size_t)f * HD);
        float a = 0.f;
#pragma unroll
        for (int i = 0; i < 16; i++) {
            float4 kv = kp[i];
            a = fmaf(q4[i].x, kv.x, a);
            a = fmaf(q4[i].y, kv.y, a);
            a = fmaf(q4[i].z, kv.z, a);
            a = fmaf(q4[i].w, kv.w, a);
        }
        s[f] = a * 0.125f;
        mx = fmaxf(mx, s[f]);
    }
    float lsum = 0.f;
#pragma unroll
    for (int f = 0; f < 16; f++) { s[f] = __expf(s[f] - mx); lsum += s[f]; }
    float inv = 1.f / lsum;
#pragma unroll
    for (int f = 0; f < 16; f++) s[f] *= inv;

#pragma unroll
    for (int ch = 0; ch < 4; ch++) {
        float4 a4[4];
#pragma unroll
        for (int i = 0; i < 4; i++) a4[i] = make_float4(0.f, 0.f, 0.f, 0.f);
#pragma unroll
        for (int f = 0; f < 16; f++) {
            float p = s[f];
            const float4* vp = (const float4*)(g_v + gb + (size_t)f * HD + ch * 16);
#pragma unroll
            for (int i = 0; i < 4; i++) {
                float4 vv = vp[i];
                a4[i].x = fmaf(p, vv.x, a4[i].x);
                a4[i].y = fmaf(p, vv.y, a4[i].y);
                a4[i].z = fmaf(p, vv.z, a4[i].z);
                a4[i].w = fmaf(p, vv.w, a4[i].w);
            }
        }
        float4* wp = (float4*)(g_w + row + ch * 16);
#pragma unroll
        for (int i = 0; i < 4; i++) wp[i] = a4[i];
    }
}

// ---------------------------------------------------------------------------
// Gather heads + bf16 split
// ---------------------------------------------------------------------------
__global__ void gather_w_k()
{
    size_t idx = (size_t)blockIdx.x * 256 + threadIdx.x;
    if (idx >= HEAD_ELEMS) return;
    int e = (int)(idx % Ddim);
    size_t bn = idx / Ddim;
    int h = e >> 6, d3 = e & 63;
    int b = (int)(bn / Ndim);
    int n = (int)(bn % Ndim);
    float v = g_w[(((size_t)(b * Hh + h)) * Ndim + n) * HD + d3];
    __nv_bfloat16 hi = __float2bfloat16(v);
    g_wf_hi[idx] = hi;
    g_wf_lo[idx] = __float2bfloat16(v - __bfloat162float(hi));
}

// ---------------------------------------------------------------------------
// Launch
// ---------------------------------------------------------------------------
extern "C" void kernel_launch(void* const* d_in, const int* in_sizes, int n_in,
                              void* d_out, int out_size)
{
    const float* x      = (const float*)d_in[0];
    const float* w_qkv  = (const float*)d_in[1];
    const float* w_proj = (const float*)d_in[2];
    const float* b_proj = (const float*)d_in[3];
    float* out = (float*)d_out;

    float* p_qkv;
    __nv_bfloat16 *p_xhi, *p_xlo, *p_qkvw_hi, *p_qkvw_lo;
    __nv_bfloat16 *p_projw_hi, *p_projw_lo, *p_wfhi, *p_wflo;
    cudaGetSymbolAddress((void**)&p_qkv, g_qkv);
    cudaGetSymbolAddress((void**)&p_xhi, g_xhi);
    cudaGetSymbolAddress((void**)&p_xlo, g_xlo);
    cudaGetSymbolAddress((void**)&p_qkvw_hi, g_wqkv_hi);
    cudaGetSymbolAddress((void**)&p_qkvw_lo, g_wqkv_lo);
    cudaGetSymbolAddress((void**)&p_projw_hi, g_wproj_hi);
    cudaGetSymbolAddress((void**)&p_projw_lo, g_wproj_lo);
    cudaGetSymbolAddress((void**)&p_wfhi, g_wf_hi);
    cudaGetSymbolAddress((void**)&p_wflo, g_wf_lo);

    cudaFuncSetAttribute(tgemm_k, cudaFuncAttributeMaxDynamicSharedMemorySize, GSMEM);

    // 0) bf16 splits of inputs / weights
    cvt_split_k<<<(unsigned)((MD_ELEMS + 255) / 256), 256>>>(x, p_xhi, p_xlo, MD_ELEMS);
    cvt_split_k<<<(unsigned)(((size_t)E3 * Ddim + 255) / 256), 256>>>(
        w_qkv, p_qkvw_hi, p_qkvw_lo, (size_t)E3 * Ddim);
    cvt_split_k<<<(unsigned)(((size_t)Ddim * Ddim + 255) / 256), 256>>>(
        w_proj, p_projw_hi, p_projw_lo, (size_t)Ddim * Ddim);

    // 1) qkv = x @ w_qkv^T   (25088 x 2304 x 768)
    tgemm_k<<<dim3(E3 / 128, Mrows / 128), 256, GSMEM>>>(
        p_xhi, p_xlo, p_qkvw_hi, p_qkvw_lo, nullptr, p_qkv, E3);

    // 2) split q/k/v
    scatter_qkv_k<<<(unsigned)((3 * HEAD_ELEMS) / 256), 256>>>();

    // 3) spatial attention
    attn_spatial_k<<<768, 256>>>();

    // 4) temporal attention
    attn_temporal_k<<<(Bdim * 6 * Ndim) / 128, 128>>>();

    // 5) interleave heads + bf16 split
    gather_w_k<<<(unsigned)(HEAD_ELEMS / 256), 256>>>();

    // 6) out = w @ w_proj^T + b_proj   (25088 x 768 x 768)
    tgemm_k<<<dim3(Ddim / 128, Mrows / 128), 256, GSMEM>>>(
        p_wfhi, p_wflo, p_projw_hi, p_projw_lo, b_proj, out, Ddim);
}

// round 6
// speedup vs baseline: 1.9673x; 1.1457x over previous
#include <cuda_runtime.h>
#include <cuda_bf16.h>
#include <cstdint>
#include <cstddef>

// ---------------------------------------------------------------------------
// Problem constants
// ---------------------------------------------------------------------------
#define Bdim  8
#define Fdim  16
#define Pdim  196
#define Ddim  768
#define Hh    12
#define HD    64
#define Ndim  3136              // F*P
#define Mrows 25088             // B*N
#define E3    2304              // 3*D

#define QKV_ELEMS  ((size_t)Mrows * E3)
#define HEAD_ELEMS ((size_t)Bdim * Hh * Ndim * HD)
#define MD_ELEMS   ((size_t)Mrows * Ddim)

// Scratch (__device__ globals; allocation-free rule)
__device__ float g_qkv[QKV_ELEMS];
__device__ float g_q[HEAD_ELEMS];
__device__ float g_k[HEAD_ELEMS];
__device__ float g_v[HEAD_ELEMS];
__device__ float g_w[HEAD_ELEMS];

__device__ __nv_bfloat16 g_xhi[MD_ELEMS];
__device__ __nv_bfloat16 g_xlo[MD_ELEMS];
__device__ __nv_bfloat16 g_wqkv_hi[(size_t)E3 * Ddim];
__device__ __nv_bfloat16 g_wqkv_lo[(size_t)E3 * Ddim];
__device__ __nv_bfloat16 g_wproj_hi[(size_t)Ddim * Ddim];
__device__ __nv_bfloat16 g_wproj_lo[(size_t)Ddim * Ddim];
__device__ __nv_bfloat16 g_wf_hi[MD_ELEMS];
__device__ __nv_bfloat16 g_wf_lo[MD_ELEMS];

// ---------------------------------------------------------------------------
// helpers
// ---------------------------------------------------------------------------
__device__ __forceinline__ void cp_async16(uint32_t dst, const void* src) {
    asm volatile("cp.async.cg.shared.global [%0], [%1], 16;"
                 :: "r"(dst), "l"(src) : "memory");
}
#define CP_COMMIT() asm volatile("cp.async.commit_group;" ::: "memory")
template <int N> __device__ __forceinline__ void cp_wait() {
    asm volatile("cp.async.wait_group %0;" :: "n"(N) : "memory");
}
__device__ __forceinline__ uint32_t smem_u32(const void* p) {
    uint32_t a;
    asm("{ .reg .u64 t; cvta.to.shared.u64 t, %1; cvt.u32.u64 %0, t; }"
        : "=r"(a) : "l"(p));
    return a;
}

__device__ __forceinline__ void mma16816(float* d,
                                         uint32_t a0, uint32_t a1, uint32_t a2, uint32_t a3,
                                         uint32_t b0, uint32_t b1) {
    asm volatile(
        "mma.sync.aligned.m16n8k16.row.col.f32.bf16.bf16.f32 "
        "{%0,%1,%2,%3}, {%4,%5,%6,%7}, {%8,%9}, {%0,%1,%2,%3};"
        : "+f"(d[0]), "+f"(d[1]), "+f"(d[2]), "+f"(d[3])
        : "r"(a0), "r"(a1), "r"(a2), "r"(a3), "r"(b0), "r"(b1));
}

__device__ __forceinline__ void ldsm4(uint32_t& r0, uint32_t& r1,
                                      uint32_t& r2, uint32_t& r3, uint32_t addr) {
    asm volatile("ldmatrix.sync.aligned.m8n8.x4.shared.b16 {%0,%1,%2,%3}, [%4];"
                 : "=r"(r0), "=r"(r1), "=r"(r2), "=r"(r3) : "r"(addr));
}

// ---------------------------------------------------------------------------
// HMMA GEMM:  C[M,N] = (Ahi+Alo)[M,768] * (Bhi+Blo)[N,768]^T (+bias)
// 128x128x32 CTA tile, 256 threads, warp grid 2(M)x4(N), warp tile 64x32.
// bf16 split (hi*hi + hi*lo + lo*hi), fp32 accumulate. ldmatrix fragment
// loads; LDK=40 padded rows (80B stride -> conflict-free ldmatrix);
// double-buffered cp.async; 2 CTAs/SM.
// ---------------------------------------------------------------------------
#define BK       32
#define LDK      40                       // padded row length (bf16)
#define TILE_B   (128 * LDK * 2)          // 10240 bytes per matrix tile
#define STAGE_B  (4 * TILE_B)             // Ahi, Alo, Bhi, Blo = 40960
#define NSTAGE   2
#define GSMEM    (NSTAGE * STAGE_B)       // 81920
#define OFF_AHI  0
#define OFF_ALO  TILE_B
#define OFF_BHI  (2 * TILE_B)
#define OFF_BLO  (3 * TILE_B)

__global__ __launch_bounds__(256, 2) void tgemm_k(
    const __nv_bfloat16* __restrict__ Ahi, const __nv_bfloat16* __restrict__ Alo,
    const __nv_bfloat16* __restrict__ Bhi, const __nv_bfloat16* __restrict__ Blo,
    const float* __restrict__ bias, float* __restrict__ C, int Nd)
{
    extern __shared__ char smem[];
    const uint32_t sb = smem_u32(smem);

    const int tid  = threadIdx.x;
    const int lane = tid & 31;
    const int wid  = tid >> 5;
    const int wm   = wid & 1;          // 0..1 : M
    const int wn   = wid >> 1;         // 0..3 : N
    const int g    = lane >> 2;        // 0..7
    const int tg   = lane & 3;         // 0..3

    const int bm = blockIdx.y * 128;
    const int bn = blockIdx.x * 128;

    // ldmatrix per-lane address components
    const int a_row = wm * 64 + (lane & 15);        // + mt*16
    const int a_kc  = (lane >> 4) * 8;              // + ks*16
    const int b_row = wn * 32 + ((lane >> 4) << 3) + (lane & 7);  // + p*16
    const int b_kc  = ((lane >> 3) & 1) * 8;        // + ks*16

    // gmem->smem loader role: 4 tiles x 64 threads, 8 granules (16B) each
    const int tile = tid >> 6;         // 0:Ahi 1:Alo 2:Bhi 3:Blo
    const int lt   = tid & 63;
    const __nv_bfloat16* src_base =
        (tile == 0) ? Ahi : (tile == 1) ? Alo : (tile == 2) ? Bhi : Blo;
    const int rowbase = (tile < 2) ? bm : bn;
    const uint32_t tile_off = tile * TILE_B;

    auto load_chunk = [&](int k0, int stage) {
        const uint32_t dbase = sb + stage * STAGE_B + tile_off;
#pragma unroll
        for (int j = 0; j < 8; j++) {
            int id  = lt + j * 64;          // 0..511
            int row = id >> 2;              // 0..127
            int gr  = id & 3;               // 16B granule within 64B row
            const void* src = src_base + (size_t)(rowbase + row) * Ddim + k0 + gr * 8;
            cp_async16(dbase + (uint32_t)(row * (LDK * 2) + gr * 16), src);
        }
        CP_COMMIT();
    };

    float acc[4][4][4];
#pragma unroll
    for (int i = 0; i < 4; i++)
#pragma unroll
        for (int j = 0; j < 4; j++)
#pragma unroll
            for (int q = 0; q < 4; q++) acc[i][j][q] = 0.f;

    load_chunk(0, 0);

    const int NCH = Ddim / BK;   // 24
    for (int c = 0; c < NCH; c++) {
        if (c + 1 < NCH) { load_chunk((c + 1) * BK, (c + 1) & 1); cp_wait<1>(); }
        else             { cp_wait<0>(); }
        __syncthreads();

        const uint32_t st = sb + (c & 1) * STAGE_B;

#pragma unroll
        for (int ks = 0; ks < 2; ks++) {
            const int kcA = ks * 16 + a_kc;
            const int kcB = ks * 16 + b_kc;
            uint32_t ah[4][4], al[4][4];
#pragma unroll
            for (int mt = 0; mt < 4; mt++) {
                uint32_t addr = st + (uint32_t)(((a_row + mt * 16) * LDK + kcA) * 2);
                ldsm4(ah[mt][0], ah[mt][1], ah[mt][2], ah[mt][3], addr + OFF_AHI);
                ldsm4(al[mt][0], al[mt][1], al[mt][2], al[mt][3], addr + OFF_ALO);
            }
#pragma unroll
            for (int p = 0; p < 2; p++) {
                uint32_t baddr = st + (uint32_t)(((b_row + p * 16) * LDK + kcB) * 2);
                uint32_t bh[2][2], bl[2][2];
                ldsm4(bh[0][0], bh[0][1], bh[1][0], bh[1][1], baddr + OFF_BHI);
                ldsm4(bl[0][0], bl[0][1], bl[1][0], bl[1][1], baddr + OFF_BLO);
#pragma unroll
                for (int q = 0; q < 2; q++) {
                    const int nt = p * 2 + q;
#pragma unroll
                    for (int mt = 0; mt < 4; mt++) {
                        mma16816(acc[mt][nt], ah[mt][0], ah[mt][1], ah[mt][2], ah[mt][3],
                                 bh[q][0], bh[q][1]);
                        mma16816(acc[mt][nt], ah[mt][0], ah[mt][1], ah[mt][2], ah[mt][3],
                                 bl[q][0], bl[q][1]);
                        mma16816(acc[mt][nt], al[mt][0], al[mt][1], al[mt][2], al[mt][3],
                                 bh[q][0], bh[q][1]);
                    }
                }
            }
        }
        __syncthreads();
    }

    // epilogue
#pragma unroll
    for (int mt = 0; mt < 4; mt++) {
        int r0 = bm + wm * 64 + mt * 16 + g;
#pragma unroll
        for (int nt = 0; nt < 4; nt++) {
            int c0 = bn + wn * 32 + nt * 8 + tg * 2;
            float b0 = 0.f, b1 = 0.f;
            if (bias) { b0 = bias[c0]; b1 = bias[c0 + 1]; }
            float2 v0 = make_float2(acc[mt][nt][0] + b0, acc[mt][nt][1] + b1);
            float2 v1 = make_float2(acc[mt][nt][2] + b0, acc[mt][nt][3] + b1);
            *(float2*)(C + (size_t)r0 * Nd + c0) = v0;
            *(float2*)(C + (size_t)(r0 + 8) * Nd + c0) = v1;
        }
    }
}

// ---------------------------------------------------------------------------
// fp32 -> bf16 hi/lo split
// ---------------------------------------------------------------------------
__global__ void cvt_split_k(const float* __restrict__ in,
                            __nv_bfloat16* __restrict__ hi,
                            __nv_bfloat16* __restrict__ lo, size_t n)
{
    size_t i = (size_t)blockIdx.x * 256 + threadIdx.x;
    if (i >= n) return;
    float v = in[i];
    __nv_bfloat16 h = __float2bfloat16(v);
    hi[i] = h;
    lo[i] = __float2bfloat16(v - __bfloat162float(h));
}

// ---------------------------------------------------------------------------
// Scatter qkv -> q/k/v in (B,12,N,64)
// ---------------------------------------------------------------------------
__global__ void scatter_qkv_k()
{
    size_t idx = (size_t)blockIdx.x * 256 + threadIdx.x;
    if (idx >= 3 * HEAD_ELEMS) return;
    int t = (int)(idx / HEAD_ELEMS);
    size_t r = idx - (size_t)t * HEAD_ELEMS;
    int bh = (int)(r / ((size_t)Ndim * HD));
    int nd = (int)(r % ((size_t)Ndim * HD));
    int n = nd >> 6, d3 = nd & 63;
    int b = bh / Hh, h = bh % Hh;
    float vv = g_qkv[((size_t)(b * Ndim + n)) * E3 + t * Ddim + h * HD + d3];
    if (t == 0)      g_q[r] = vv;
    else if (t == 1) g_k[r] = vv;
    else             g_v[r] = vv;
}

// ---------------------------------------------------------------------------
// Spatial attention: 768 groups of 196 rows (heads 0..5), float4 version.
// ---------------------------------------------------------------------------
__global__ __launch_bounds__(256) void attn_spatial_k()
{
    __shared__ float4 K4[64][16];
    __shared__ float4 V4[64][16];

    const int g = blockIdx.x;
    const int b = g / 96;
    const int h = (g % 96) / 16;
    const int f = g % 16;
    const size_t base = (((size_t)(b * Hh + h)) * Ndim + f * Pdim) * HD;

    const int tid = threadIdx.x;
    const bool active = tid < Pdim;

    float4 q4[16], a4[16];
    float mx = -1e30f, lsum = 0.f;
    if (active) {
        const float4* qp = (const float4*)(g_q + base + (size_t)tid * HD);
#pragma unroll
        for (int i = 0; i < 16; i++) q4[i] = qp[i];
#pragma unroll
        for (int i = 0; i < 16; i++) a4[i] = make_float4(0.f, 0.f, 0.f, 0.f);
    }

    const float scale = 0.125f;

    for (int j0 = 0; j0 < Pdim; j0 += 64) {
        int cnt = Pdim - j0; if (cnt > 64) cnt = 64;
        __syncthreads();
        {
            const float4* kp = (const float4*)(g_k + base + (size_t)j0 * HD);
            const float4* vp = (const float4*)(g_v + base + (size_t)j0 * HD);
            for (int t = tid; t < cnt * 16; t += 256) {
                K4[t >> 4][t & 15] = kp[t];
                V4[t >> 4][t & 15] = vp[t];
            }
        }
        __syncthreads();
        if (active) {
            for (int j = 0; j < cnt; j++) {
                float s = 0.f;
#pragma unroll
                for (int i = 0; i < 16; i++) {
                    float4 kv = K4[j][i];
                    s = fmaf(q4[i].x, kv.x, s);
                    s = fmaf(q4[i].y, kv.y, s);
                    s = fmaf(q4[i].z, kv.z, s);
                    s = fmaf(q4[i].w, kv.w, s);
                }
                s *= scale;
                if (s <= mx) {
                    float p = __expf(s - mx);
                    lsum += p;
#pragma unroll
                    for (int i = 0; i < 16; i++) {
                        float4 vv = V4[j][i];
                        a4[i].x = fmaf(p, vv.x, a4[i].x);
                        a4[i].y = fmaf(p, vv.y, a4[i].y);
                        a4[i].z = fmaf(p, vv.z, a4[i].z);
                        a4[i].w = fmaf(p, vv.w, a4[i].w);
                    }
                } else {
                    float corr = __expf(mx - s);
                    lsum = lsum * corr + 1.f;
#pragma unroll
                    for (int i = 0; i < 16; i++) {
                        float4 vv = V4[j][i];
                        a4[i].x = fmaf(a4[i].x, corr, vv.x);
                        a4[i].y = fmaf(a4[i].y, corr, vv.y);
                        a4[i].z = fmaf(a4[i].z, corr, vv.z);
                        a4[i].w = fmaf(a4[i].w, corr, vv.w);
                    }
                    mx = s;
                }
            }
        }
    }

    if (active) {
        float inv = 1.f / lsum;
        float4* wp = (float4*)(g_w + base + (size_t)tid * HD);
#pragma unroll
        for (int i = 0; i < 16; i++) {
            float4 o;
            o.x = a4[i].x * inv; o.y = a4[i].y * inv;
            o.z = a4[i].z * inv; o.w = a4[i].w * inv;
            wp[i] = o;
        }
    }
}

// ---------------------------------------------------------------------------
// Temporal attention: heads 6..11, groups of 16 rows. float4 + chunked output.
// ---------------------------------------------------------------------------
__global__ __launch_bounds__(128) void attn_temporal_k()
{
    int tid = blockIdx.x * 128 + threadIdx.x;
    const int TOT = Bdim * 6 * Ndim;
    if (tid >= TOT) return;
    int b = tid / (6 * Ndim);
    int rr = tid - b * (6 * Ndim);
    int h = 6 + rr / Ndim;
    int n = rr % Ndim;
    int n0 = n & ~15;
    size_t row = (((size_t)(b * Hh + h)) * Ndim + n) * HD;
    size_t gb  = (((size_t)(b * Hh + h)) * Ndim + n0) * HD;

    float4 q4[16];
    const float4* qp = (const float4*)(g_q + row);
#pragma unroll
    for (int i = 0; i < 16; i++) q4[i] = qp[i];

    float s[16];
    float mx = -1e30f;
#pragma unroll
    for (int f = 0; f < 16; f++) {
        const float4* kp = (const float4*)(g_k + gb + (size_t)f * HD);
        float a = 0.f;
#pragma unroll
        for (int i = 0; i < 16; i++) {
            float4 kv = kp[i];
            a = fmaf(q4[i].x, kv.x, a);
            a = fmaf(q4[i].y, kv.y, a);
            a = fmaf(q4[i].z, kv.z, a);
            a = fmaf(q4[i].w, kv.w, a);
        }
        s[f] = a * 0.125f;
        mx = fmaxf(mx, s[f]);
    }
    float lsum = 0.f;
#pragma unroll
    for (int f = 0; f < 16; f++) { s[f] = __expf(s[f] - mx); lsum += s[f]; }
    float inv = 1.f / lsum;
#pragma unroll
    for (int f = 0; f < 16; f++) s[f] *= inv;

#pragma unroll
    for (int ch = 0; ch < 4; ch++) {
        float4 a4[4];
#pragma unroll
        for (int i = 0; i < 4; i++) a4[i] = make_float4(0.f, 0.f, 0.f, 0.f);
#pragma unroll
        for (int f = 0; f < 16; f++) {
            float p = s[f];
            const float4* vp = (const float4*)(g_v + gb + (size_t)f * HD + ch * 16);
#pragma unroll
            for (int i = 0; i < 4; i++) {
                float4 vv = vp[i];
                a4[i].x = fmaf(p, vv.x, a4[i].x);
                a4[i].y = fmaf(p, vv.y, a4[i].y);
                a4[i].z = fmaf(p, vv.z, a4[i].z);
                a4[i].w = fmaf(p, vv.w, a4[i].w);
            }
        }
        float4* wp = (float4*)(g_w + row + ch * 16);
#pragma unroll
        for (int i = 0; i < 4; i++) wp[i] = a4[i];
    }
}

// ---------------------------------------------------------------------------
// Gather heads + bf16 split
// ---------------------------------------------------------------------------
__global__ void gather_w_k()
{
    size_t idx = (size_t)blockIdx.x * 256 + threadIdx.x;
    if (idx >= HEAD_ELEMS) return;
    int e = (int)(idx % Ddim);
    size_t bn = idx / Ddim;
    int h = e >> 6, d3 = e & 63;
    int b = (int)(bn / Ndim);
    int n = (int)(bn % Ndim);
    float v = g_w[(((size_t)(b * Hh + h)) * Ndim + n) * HD + d3];
    __nv_bfloat16 hi = __float2bfloat16(v);
    g_wf_hi[idx] = hi;
    g_wf_lo[idx] = __float2bfloat16(v - __bfloat162float(hi));
}

// ---------------------------------------------------------------------------
// Launch
// ---------------------------------------------------------------------------
extern "C" void kernel_launch(void* const* d_in, const int* in_sizes, int n_in,
                              void* d_out, int out_size)
{
    const float* x      = (const float*)d_in[0];
    const float* w_qkv  = (const float*)d_in[1];
    const float* w_proj = (const float*)d_in[2];
    const float* b_proj = (const float*)d_in[3];
    float* out = (float*)d_out;

    float* p_qkv;
    __nv_bfloat16 *p_xhi, *p_xlo, *p_qkvw_hi, *p_qkvw_lo;
    __nv_bfloat16 *p_projw_hi, *p_projw_lo, *p_wfhi, *p_wflo;
    cudaGetSymbolAddress((void**)&p_qkv, g_qkv);
    cudaGetSymbolAddress((void**)&p_xhi, g_xhi);
    cudaGetSymbolAddress((void**)&p_xlo, g_xlo);
    cudaGetSymbolAddress((void**)&p_qkvw_hi, g_wqkv_hi);
    cudaGetSymbolAddress((void**)&p_qkvw_lo, g_wqkv_lo);
    cudaGetSymbolAddress((void**)&p_projw_hi, g_wproj_hi);
    cudaGetSymbolAddress((void**)&p_projw_lo, g_wproj_lo);
    cudaGetSymbolAddress((void**)&p_wfhi, g_wf_hi);
    cudaGetSymbolAddress((void**)&p_wflo, g_wf_lo);

    cudaFuncSetAttribute(tgemm_k, cudaFuncAttributeMaxDynamicSharedMemorySize, GSMEM);

    // 0) bf16 splits of inputs / weights
    cvt_split_k<<<(unsigned)((MD_ELEMS + 255) / 256), 256>>>(x, p_xhi, p_xlo, MD_ELEMS);
    cvt_split_k<<<(unsigned)(((size_t)E3 * Ddim + 255) / 256), 256>>>(
        w_qkv, p_qkvw_hi, p_qkvw_lo, (size_t)E3 * Ddim);
    cvt_split_k<<<(unsigned)(((size_t)Ddim * Ddim + 255) / 256), 256>>>(
        w_proj, p_projw_hi, p_projw_lo, (size_t)Ddim * Ddim);

    // 1) qkv = x @ w_qkv^T   (25088 x 2304 x 768)
    tgemm_k<<<dim3(E3 / 128, Mrows / 128), 256, GSMEM>>>(
        p_xhi, p_xlo, p_qkvw_hi, p_qkvw_lo, nullptr, p_qkv, E3);

    // 2) split q/k/v
    scatter_qkv_k<<<(unsigned)((3 * HEAD_ELEMS) / 256), 256>>>();

    // 3) spatial attention
    attn_spatial_k<<<768, 256>>>();

    // 4) temporal attention
    attn_temporal_k<<<(Bdim * 6 * Ndim) / 128, 128>>>();

    // 5) interleave heads + bf16 split
    gather_w_k<<<(unsigned)(HEAD_ELEMS / 256), 256>>>();

    // 6) out = w @ w_proj^T + b_proj   (25088 x 768 x 768)
    tgemm_k<<<dim3(Ddim / 128, Mrows / 128), 256, GSMEM>>>(
        p_wfhi, p_wflo, p_projw_hi, p_projw_lo, b_proj, out, Ddim);
}

// round 7
// speedup vs baseline: 2.0981x; 1.0665x over previous
#include <cuda_runtime.h>
#include <cuda_bf16.h>
#include <cstdint>
#include <cstddef>

// ---------------------------------------------------------------------------
// Problem constants
// ---------------------------------------------------------------------------
#define Bdim  8
#define Fdim  16
#define Pdim  196
#define Ddim  768
#define Hh    12
#define HD    64
#define Ndim  3136              // F*P
#define Mrows 25088             // B*N
#define E3    2304              // 3*D

#define HEAD_ELEMS ((size_t)Bdim * Hh * Ndim * HD)
#define MD_ELEMS   ((size_t)Mrows * Ddim)

// Scratch (__device__ globals; allocation-free rule)
__device__ float g_q[HEAD_ELEMS];
__device__ float g_k[HEAD_ELEMS];
__device__ float g_v[HEAD_ELEMS];

__device__ __nv_bfloat16 g_xhi[MD_ELEMS];
__device__ __nv_bfloat16 g_xlo[MD_ELEMS];
__device__ __nv_bfloat16 g_wqkv_hi[(size_t)E3 * Ddim];
__device__ __nv_bfloat16 g_wqkv_lo[(size_t)E3 * Ddim];
__device__ __nv_bfloat16 g_wproj_hi[(size_t)Ddim * Ddim];
__device__ __nv_bfloat16 g_wproj_lo[(size_t)Ddim * Ddim];
__device__ __nv_bfloat16 g_wf_hi[MD_ELEMS];
__device__ __nv_bfloat16 g_wf_lo[MD_ELEMS];

// ---------------------------------------------------------------------------
// helpers
// ---------------------------------------------------------------------------
__device__ __forceinline__ void cp_async16(uint32_t dst, const void* src) {
    asm volatile("cp.async.cg.shared.global [%0], [%1], 16;"
                 :: "r"(dst), "l"(src) : "memory");
}
#define CP_COMMIT() asm volatile("cp.async.commit_group;" ::: "memory")
template <int N> __device__ __forceinline__ void cp_wait() {
    asm volatile("cp.async.wait_group %0;" :: "n"(N) : "memory");
}
__device__ __forceinline__ uint32_t smem_u32(const void* p) {
    uint32_t a;
    asm("{ .reg .u64 t; cvta.to.shared.u64 t, %1; cvt.u32.u64 %0, t; }"
        : "=r"(a) : "l"(p));
    return a;
}

__device__ __forceinline__ void mma16816(float* d,
                                         uint32_t a0, uint32_t a1, uint32_t a2, uint32_t a3,
                                         uint32_t b0, uint32_t b1) {
    asm volatile(
        "mma.sync.aligned.m16n8k16.row.col.f32.bf16.bf16.f32 "
        "{%0,%1,%2,%3}, {%4,%5,%6,%7}, {%8,%9}, {%0,%1,%2,%3};"
        : "+f"(d[0]), "+f"(d[1]), "+f"(d[2]), "+f"(d[3])
        : "r"(a0), "r"(a1), "r"(a2), "r"(a3), "r"(b0), "r"(b1));
}

__device__ __forceinline__ void ldsm4(uint32_t& r0, uint32_t& r1,
                                      uint32_t& r2, uint32_t& r3, uint32_t addr) {
    asm volatile("ldmatrix.sync.aligned.m8n8.x4.shared.b16 {%0,%1,%2,%3}, [%4];"
                 : "=r"(r0), "=r"(r1), "=r"(r2), "=r"(r3) : "r"(addr));
}

// ---------------------------------------------------------------------------
// HMMA GEMM:  C = (Ahi+Alo)[M,768] * (Bhi+Blo)[N,768]^T
// 128x128x32 CTA tile, 256 threads, warp grid 2(M)x4(N), warp tile 64x32.
// mode 0: scatter epilogue into q/k/v head layout (no bias)
// mode 1: normal C[M,Nd] + bias
// ---------------------------------------------------------------------------
#define BK       32
#define LDK      40                       // padded row length (bf16)
#define TILE_B   (128 * LDK * 2)          // 10240 bytes per matrix tile
#define STAGE_B  (4 * TILE_B)             // Ahi, Alo, Bhi, Blo = 40960
#define GSMEM    (2 * STAGE_B)            // 81920
#define OFF_AHI  0
#define OFF_ALO  TILE_B
#define OFF_BHI  (2 * TILE_B)
#define OFF_BLO  (3 * TILE_B)

__global__ __launch_bounds__(256, 2) void tgemm_k(
    const __nv_bfloat16* __restrict__ Ahi, const __nv_bfloat16* __restrict__ Alo,
    const __nv_bfloat16* __restrict__ Bhi, const __nv_bfloat16* __restrict__ Blo,
    const float* __restrict__ bias, float* __restrict__ C, int Nd, int mode,
    float* __restrict__ Qo, float* __restrict__ Ko, float* __restrict__ Vo)
{
    extern __shared__ char smem[];
    const uint32_t sb = smem_u32(smem);

    const int tid  = threadIdx.x;
    const int lane = tid & 31;
    const int wid  = tid >> 5;
    const int wm   = wid & 1;          // 0..1 : M
    const int wn   = wid >> 1;         // 0..3 : N
    const int g    = lane >> 2;        // 0..7
    const int tg   = lane & 3;         // 0..3

    const int bm = blockIdx.y * 128;
    const int bn = blockIdx.x * 128;

    // ldmatrix per-lane address components
    const int a_row = wm * 64 + (lane & 15);        // + mt*16
    const int a_kc  = (lane >> 4) * 8;              // + ks*16
    const int b_row = wn * 32 + ((lane >> 4) << 3) + (lane & 7);  // + p*16
    const int b_kc  = ((lane >> 3) & 1) * 8;        // + ks*16

    // gmem->smem loader role: 4 tiles x 64 threads, 8 granules (16B) each
    const int tile = tid >> 6;         // 0:Ahi 1:Alo 2:Bhi 3:Blo
    const int lt   = tid & 63;
    const __nv_bfloat16* src_base =
        (tile == 0) ? Ahi : (tile == 1) ? Alo : (tile == 2) ? Bhi : Blo;
    const int rowbase = (tile < 2) ? bm : bn;
    const uint32_t tile_off = tile * TILE_B;

    auto load_chunk = [&](int k0, int stage) {
        const uint32_t dbase = sb + stage * STAGE_B + tile_off;
#pragma unroll
        for (int j = 0; j < 8; j++) {
            int id  = lt + j * 64;          // 0..511
            int row = id >> 2;              // 0..127
            int gr  = id & 3;               // 16B granule within 64B row
            const void* src = src_base + (size_t)(rowbase + row) * Ddim + k0 + gr * 8;
            cp_async16(dbase + (uint32_t)(row * (LDK * 2) + gr * 16), src);
        }
        CP_COMMIT();
    };

    float acc[4][4][4];
#pragma unroll
    for (int i = 0; i < 4; i++)
#pragma unroll
        for (int j = 0; j < 4; j++)
#pragma unroll
            for (int q = 0; q < 4; q++) acc[i][j][q] = 0.f;

    load_chunk(0, 0);

    const int NCH = Ddim / BK;   // 24
    for (int c = 0; c < NCH; c++) {
        if (c + 1 < NCH) { load_chunk((c + 1) * BK, (c + 1) & 1); cp_wait<1>(); }
        else             { cp_wait<0>(); }
        __syncthreads();

        const uint32_t st = sb + (c & 1) * STAGE_B;

#pragma unroll
        for (int ks = 0; ks < 2; ks++) {
            const int kcA = ks * 16 + a_kc;
            const int kcB = ks * 16 + b_kc;
            uint32_t ah[4][4], al[4][4];
#pragma unroll
            for (int mt = 0; mt < 4; mt++) {
                uint32_t addr = st + (uint32_t)(((a_row + mt * 16) * LDK + kcA) * 2);
                ldsm4(ah[mt][0], ah[mt][1], ah[mt][2], ah[mt][3], addr + OFF_AHI);
                ldsm4(al[mt][0], al[mt][1], al[mt][2], al[mt][3], addr + OFF_ALO);
            }
#pragma unroll
            for (int p = 0; p < 2; p++) {
                uint32_t baddr = st + (uint32_t)(((b_row + p * 16) * LDK + kcB) * 2);
                uint32_t bh[2][2], bl[2][2];
                ldsm4(bh[0][0], bh[0][1], bh[1][0], bh[1][1], baddr + OFF_BHI);
                ldsm4(bl[0][0], bl[0][1], bl[1][0], bl[1][1], baddr + OFF_BLO);
#pragma unroll
                for (int q = 0; q < 2; q++) {
                    const int nt = p * 2 + q;
#pragma unroll
                    for (int mt = 0; mt < 4; mt++) {
                        mma16816(acc[mt][nt], ah[mt][0], ah[mt][1], ah[mt][2], ah[mt][3],
                                 bh[q][0], bh[q][1]);
                        mma16816(acc[mt][nt], ah[mt][0], ah[mt][1], ah[mt][2], ah[mt][3],
                                 bl[q][0], bl[q][1]);
                        mma16816(acc[mt][nt], al[mt][0], al[mt][1], al[mt][2], al[mt][3],
                                 bh[q][0], bh[q][1]);
                    }
                }
            }
        }
        __syncthreads();
    }

    // epilogue
    if (mode == 1) {
#pragma unroll
        for (int mt = 0; mt < 4; mt++) {
            int r0 = bm + wm * 64 + mt * 16 + g;
#pragma unroll
            for (int nt = 0; nt < 4; nt++) {
                int c0 = bn + wn * 32 + nt * 8 + tg * 2;
                float b0 = bias[c0], b1 = bias[c0 + 1];
                float2 v0 = make_float2(acc[mt][nt][0] + b0, acc[mt][nt][1] + b1);
                float2 v1 = make_float2(acc[mt][nt][2] + b0, acc[mt][nt][3] + b1);
                *(float2*)(C + (size_t)r0 * Nd + c0) = v0;
                *(float2*)(C + (size_t)(r0 + 8) * Nd + c0) = v1;
            }
        }
    } else {
        // scatter into q/k/v (B,12,N,64) head layout
#pragma unroll
        for (int nt = 0; nt < 4; nt++) {
            int c0 = bn + wn * 32 + nt * 8 + tg * 2;
            int t = c0 / Ddim;
            int rem = c0 - t * Ddim;
            int h = rem >> 6, d = rem & 63;
            float* dst = (t == 0) ? Qo : (t == 1) ? Ko : Vo;
#pragma unroll
            for (int mt = 0; mt < 4; mt++) {
                int r0 = bm + wm * 64 + mt * 16 + g;
#pragma unroll
                for (int rr = 0; rr < 2; rr++) {
                    int r = r0 + rr * 8;
                    int b = r / Ndim;
                    int n = r - b * Ndim;
                    size_t off = (((size_t)(b * Hh + h)) * Ndim + n) * HD + d;
                    float2 v = make_float2(acc[mt][nt][2 * rr], acc[mt][nt][2 * rr + 1]);
                    *(float2*)(dst + off) = v;
                }
            }
        }
    }
}

// ---------------------------------------------------------------------------
// fp32 -> bf16 hi/lo split
// ---------------------------------------------------------------------------
__global__ void cvt_split_k(const float* __restrict__ in,
                            __nv_bfloat16* __restrict__ hi,
                            __nv_bfloat16* __restrict__ lo, size_t n)
{
    size_t i = (size_t)blockIdx.x * 256 + threadIdx.x;
    if (i >= n) return;
    float v = in[i];
    __nv_bfloat16 h = __float2bfloat16(v);
    hi[i] = h;
    lo[i] = __float2bfloat16(v - __bfloat162float(h));
}

// ---------------------------------------------------------------------------
// Spatial attention: 768 groups of 196 rows (heads 0..5), float4 version.
// Output written straight into g_wf_hi/lo head-interleaved layout.
// ---------------------------------------------------------------------------
__global__ __launch_bounds__(256) void attn_spatial_k()
{
    __shared__ float4 K4[64][16];
    __shared__ float4 V4[64][16];

    const int g = blockIdx.x;
    const int b = g / 96;
    const int h = (g % 96) / 16;
    const int f = g % 16;
    const size_t base = (((size_t)(b * Hh + h)) * Ndim + f * Pdim) * HD;

    const int tid = threadIdx.x;
    const bool active = tid < Pdim;

    float4 q4[16], a4[16];
    float mx = -1e30f, lsum = 0.f;
    if (active) {
        const float4* qp = (const float4*)(g_q + base + (size_t)tid * HD);
#pragma unroll
        for (int i = 0; i < 16; i++) q4[i] = qp[i];
#pragma unroll
        for (int i = 0; i < 16; i++) a4[i] = make_float4(0.f, 0.f, 0.f, 0.f);
    }

    const float scale = 0.125f;

    for (int j0 = 0; j0 < Pdim; j0 += 64) {
        int cnt = Pdim - j0; if (cnt > 64) cnt = 64;
        __syncthreads();
        {
            const float4* kp = (const float4*)(g_k + base + (size_t)j0 * HD);
            const float4* vp = (const float4*)(g_v + base + (size_t)j0 * HD);
            for (int t = tid; t < cnt * 16; t += 256) {
                K4[t >> 4][t & 15] = kp[t];
                V4[t >> 4][t & 15] = vp[t];
            }
        }
        __syncthreads();
        if (active) {
            for (int j = 0; j < cnt; j++) {
                float s = 0.f;
#pragma unroll
                for (int i = 0; i < 16; i++) {
                    float4 kv = K4[j][i];
                    s = fmaf(q4[i].x, kv.x, s);
                    s = fmaf(q4[i].y, kv.y, s);
                    s = fmaf(q4[i].z, kv.z, s);
                    s = fmaf(q4[i].w, kv.w, s);
                }
                s *= scale;
                if (s <= mx) {
                    float p = __expf(s - mx);
                    lsum += p;
#pragma unroll
                    for (int i = 0; i < 16; i++) {
                        float4 vv = V4[j][i];
                        a4[i].x = fmaf(p, vv.x, a4[i].x);
                        a4[i].y = fmaf(p, vv.y, a4[i].y);
                        a4[i].z = fmaf(p, vv.z, a4[i].z);
                        a4[i].w = fmaf(p, vv.w, a4[i].w);
                    }
                } else {
                    float corr = __expf(mx - s);
                    lsum = lsum * corr + 1.f;
#pragma unroll
                    for (int i = 0; i < 16; i++) {
                        float4 vv = V4[j][i];
                        a4[i].x = fmaf(a4[i].x, corr, vv.x);
                        a4[i].y = fmaf(a4[i].y, corr, vv.y);
                        a4[i].z = fmaf(a4[i].z, corr, vv.z);
                        a4[i].w = fmaf(a4[i].w, corr, vv.w);
                    }
                    mx = s;
                }
            }
        }
    }

    if (active) {
        float inv = 1.f / lsum;
        const int nglob = f * Pdim + tid;
        const size_t obase = ((size_t)b * Ndim + nglob) * Ddim + h * HD;
#pragma unroll
        for (int i = 0; i < 16; i++) {
            float vals[4] = { a4[i].x * inv, a4[i].y * inv, a4[i].z * inv, a4[i].w * inv };
#pragma unroll
            for (int j = 0; j < 4; j += 2) {
                float v0 = vals[j], v1 = vals[j + 1];
                __nv_bfloat16 h0 = __float2bfloat16(v0);
                __nv_bfloat16 h1 = __float2bfloat16(v1);
                __nv_bfloat162 hv; hv.x = h0; hv.y = h1;
                __nv_bfloat162 lv;
                lv.x = __float2bfloat16(v0 - __bfloat162float(h0));
                lv.y = __float2bfloat16(v1 - __bfloat162float(h1));
                *(__nv_bfloat162*)(g_wf_hi + obase + i * 4 + j) = hv;
                *(__nv_bfloat162*)(g_wf_lo + obase + i * 4 + j) = lv;
            }
        }
    }
}

// ---------------------------------------------------------------------------
// Temporal attention: heads 6..11, groups of 16 rows. Writes g_wf directly.
// ---------------------------------------------------------------------------
__global__ __launch_bounds__(128) void attn_temporal_k()
{
    int tid = blockIdx.x * 128 + threadIdx.x;
    const int TOT = Bdim * 6 * Ndim;
    if (tid >= TOT) return;
    int b = tid / (6 * Ndim);
    int rr = tid - b * (6 * Ndim);
    int h = 6 + rr / Ndim;
    int n = rr % Ndim;
    int n0 = n & ~15;
    size_t row = (((size_t)(b * Hh + h)) * Ndim + n) * HD;
    size_t gb  = (((size_t)(b * Hh + h)) * Ndim + n0) * HD;

    float4 q4[16];
    const float4* qp = (const float4*)(g_q + row);
#pragma unroll
    for (int i = 0; i < 16; i++) q4[i] = qp[i];

    float s[16];
    float mx = -1e30f;
#pragma unroll
    for (int f = 0; f < 16; f++) {
        const float4* kp = (const float4*)(g_k + gb + (size_t)f * HD);
        float a = 0.f;
#pragma unroll
        for (int i = 0; i < 16; i++) {
            float4 kv = kp[i];
            a = fmaf(q4[i].x, kv.x, a);
            a = fmaf(q4[i].y, kv.y, a);
            a = fmaf(q4[i].z, kv.z, a);
            a = fmaf(q4[i].w, kv.w, a);
        }
        s[f] = a * 0.125f;
        mx = fmaxf(mx, s[f]);
    }
    float lsum = 0.f;
#pragma unroll
    for (int f = 0; f < 16; f++) { s[f] = __expf(s[f] - mx); lsum += s[f]; }
    float inv = 1.f / lsum;
#pragma unroll
    for (int f = 0; f < 16; f++) s[f] *= inv;

    const size_t obase = ((size_t)b * Ndim + n) * Ddim + h * HD;
#pragma unroll
    for (int ch = 0; ch < 4; ch++) {
        float4 a4[4];
#pragma unroll
        for (int i = 0; i < 4; i++) a4[i] = make_float4(0.f, 0.f, 0.f, 0.f);
#pragma unroll
        for (int f = 0; f < 16; f++) {
            float p = s[f];
            const float4* vp = (const float4*)(g_v + gb + (size_t)f * HD + ch * 16);
#pragma unroll
            for (int i = 0; i < 4; i++) {
                float4 vv = vp[i];
                a4[i].x = fmaf(p, vv.x, a4[i].x);
                a4[i].y = fmaf(p, vv.y, a4[i].y);
                a4[i].z = fmaf(p, vv.z, a4[i].z);
                a4[i].w = fmaf(p, vv.w, a4[i].w);
            }
        }
#pragma unroll
        for (int i = 0; i < 4; i++) {
            float vals[4] = { a4[i].x, a4[i].y, a4[i].z, a4[i].w };
#pragma unroll
            for (int j = 0; j < 4; j += 2) {
                float v0 = vals[j], v1 = vals[j + 1];
                __nv_bfloat16 h0 = __float2bfloat16(v0);
                __nv_bfloat16 h1 = __float2bfloat16(v1);
                __nv_bfloat162 hv; hv.x = h0; hv.y = h1;
                __nv_bfloat162 lv;
                lv.x = __float2bfloat16(v0 - __bfloat162float(h0));
                lv.y = __float2bfloat16(v1 - __bfloat162float(h1));
                size_t o = obase + ch * 16 + i * 4 + j;
                *(__nv_bfloat162*)(g_wf_hi + o) = hv;
                *(__nv_bfloat162*)(g_wf_lo + o) = lv;
            }
        }
    }
}

// ---------------------------------------------------------------------------
// Launch
// ---------------------------------------------------------------------------
extern "C" void kernel_launch(void* const* d_in, const int* in_sizes, int n_in,
                              void* d_out, int out_size)
{
    const float* x      = (const float*)d_in[0];
    const float* w_qkv  = (const float*)d_in[1];
    const float* w_proj = (const float*)d_in[2];
    const float* b_proj = (const float*)d_in[3];
    float* out = (float*)d_out;

    float *p_q, *p_k, *p_v;
    __nv_bfloat16 *p_xhi, *p_xlo, *p_qkvw_hi, *p_qkvw_lo;
    __nv_bfloat16 *p_projw_hi, *p_projw_lo, *p_wfhi, *p_wflo;
    cudaGetSymbolAddress((void**)&p_q, g_q);
    cudaGetSymbolAddress((void**)&p_k, g_k);
    cudaGetSymbolAddress((void**)&p_v, g_v);
    cudaGetSymbolAddress((void**)&p_xhi, g_xhi);
    cudaGetSymbolAddress((void**)&p_xlo, g_xlo);
    cudaGetSymbolAddress((void**)&p_qkvw_hi, g_wqkv_hi);
    cudaGetSymbolAddress((void**)&p_qkvw_lo, g_wqkv_lo);
    cudaGetSymbolAddress((void**)&p_projw_hi, g_wproj_hi);
    cudaGetSymbolAddress((void**)&p_projw_lo, g_wproj_lo);
    cudaGetSymbolAddress((void**)&p_wfhi, g_wf_hi);
    cudaGetSymbolAddress((void**)&p_wflo, g_wf_lo);

    cudaFuncSetAttribute(tgemm_k, cudaFuncAttributeMaxDynamicSharedMemorySize, GSMEM);

    // 0) bf16 splits of inputs / weights
    cvt_split_k<<<(unsigned)((MD_ELEMS + 255) / 256), 256>>>(x, p_xhi, p_xlo, MD_ELEMS);
    cvt_split_k<<<(unsigned)(((size_t)E3 * Ddim + 255) / 256), 256>>>(
        w_qkv, p_qkvw_hi, p_qkvw_lo, (size_t)E3 * Ddim);
    cvt_split_k<<<(unsigned)(((size_t)Ddim * Ddim + 255) / 256), 256>>>(
        w_proj, p_projw_hi, p_projw_lo, (size_t)Ddim * Ddim);

    // 1) qkv GEMM with fused scatter into q/k/v head layout
    tgemm_k<<<dim3(E3 / 128, Mrows / 128), 256, GSMEM>>>(
        p_xhi, p_xlo, p_qkvw_hi, p_qkvw_lo, nullptr, nullptr, E3, 0,
        p_q, p_k, p_v);

    // 2) spatial attention (writes g_wf_hi/lo directly)
    attn_spatial_k<<<768, 256>>>();

    // 3) temporal attention (writes g_wf_hi/lo directly)
    attn_temporal_k<<<(Bdim * 6 * Ndim) / 128, 128>>>();

    // 4) out = wf @ w_proj^T + b_proj
    tgemm_k<<<dim3(Ddim / 128, Mrows / 128), 256, GSMEM>>>(
        p_wfhi, p_wflo, p_projw_hi, p_projw_lo, b_proj, out, Ddim, 1,
        nullptr, nullptr, nullptr);
}

// round 8
// speedup vs baseline: 2.1374x; 1.0188x over previous
#include <cuda_runtime.h>
#include <cuda_bf16.h>
#include <cstdint>
#include <cstddef>

// ---------------------------------------------------------------------------
// Problem constants
// ---------------------------------------------------------------------------
#define Bdim  8
#define Fdim  16
#define Pdim  196
#define Ddim  768
#define Hh    12
#define HD    64
#define Ndim  3136              // F*P
#define Mrows 25088             // B*N
#define E3    2304              // 3*D

#define HEAD_ELEMS ((size_t)Bdim * Hh * Ndim * HD)
#define MD_ELEMS   ((size_t)Mrows * Ddim)

// Scratch (__device__ globals; allocation-free rule)
__device__ float g_q[HEAD_ELEMS];
__device__ float g_k[HEAD_ELEMS];
__device__ float g_v[HEAD_ELEMS];

__device__ __nv_bfloat16 g_xhi[MD_ELEMS];
__device__ __nv_bfloat16 g_xlo[MD_ELEMS];
__device__ __nv_bfloat16 g_wqkv_hi[(size_t)E3 * Ddim];
__device__ __nv_bfloat16 g_wqkv_lo[(size_t)E3 * Ddim];
__device__ __nv_bfloat16 g_wproj_hi[(size_t)Ddim * Ddim];
__device__ __nv_bfloat16 g_wproj_lo[(size_t)Ddim * Ddim];
__device__ __nv_bfloat16 g_wf_hi[MD_ELEMS];
__device__ __nv_bfloat16 g_wf_lo[MD_ELEMS];

// ---------------------------------------------------------------------------
// helpers
// ---------------------------------------------------------------------------
__device__ __forceinline__ void cp_async16(uint32_t dst, const void* src) {
    asm volatile("cp.async.cg.shared.global [%0], [%1], 16;"
                 :: "r"(dst), "l"(src) : "memory");
}
#define CP_COMMIT() asm volatile("cp.async.commit_group;" ::: "memory")
template <int N> __device__ __forceinline__ void cp_wait() {
    asm volatile("cp.async.wait_group %0;" :: "n"(N) : "memory");
}
__device__ __forceinline__ uint32_t smem_u32(const void* p) {
    uint32_t a;
    asm("{ .reg .u64 t; cvta.to.shared.u64 t, %1; cvt.u32.u64 %0, t; }"
        : "=r"(a) : "l"(p));
    return a;
}

__device__ __forceinline__ void mma16816(float* d,
                                         uint32_t a0, uint32_t a1, uint32_t a2, uint32_t a3,
                                         uint32_t b0, uint32_t b1) {
    asm volatile(
        "mma.sync.aligned.m16n8k16.row.col.f32.bf16.bf16.f32 "
        "{%0,%1,%2,%3}, {%4,%5,%6,%7}, {%8,%9}, {%0,%1,%2,%3};"
        : "+f"(d[0]), "+f"(d[1]), "+f"(d[2]), "+f"(d[3])
        : "r"(a0), "r"(a1), "r"(a2), "r"(a3), "r"(b0), "r"(b1));
}

__device__ __forceinline__ void ldsm4(uint32_t& r0, uint32_t& r1,
                                      uint32_t& r2, uint32_t& r3, uint32_t addr) {
    asm volatile("ldmatrix.sync.aligned.m8n8.x4.shared.b16 {%0,%1,%2,%3}, [%4];"
                 : "=r"(r0), "=r"(r1), "=r"(r2), "=r"(r3) : "r"(addr));
}

// ---------------------------------------------------------------------------
// HMMA GEMM:  C = (Ahi+Alo)[M,768] * (Bhi+Blo)[N,768]^T
// 128x128x32 CTA tile, 256 threads, warp grid 2(M)x4(N), warp tile 64x32.
// Single __syncthreads per chunk: loads for chunk c+1 are issued AFTER the
// barrier of chunk c, so they cannot overwrite the buffer other warps were
// reading in chunk c-1.
// mode 0: scatter epilogue into q/k/v head layout (no bias)
// mode 1: normal C[M,Nd] + bias
// ---------------------------------------------------------------------------
#define BK       32
#define LDK      40                       // padded row length (bf16)
#define TILE_B   (128 * LDK * 2)          // 10240 bytes per matrix tile
#define STAGE_B  (4 * TILE_B)             // Ahi, Alo, Bhi, Blo = 40960
#define GSMEM    (2 * STAGE_B)            // 81920
#define OFF_AHI  0
#define OFF_ALO  TILE_B
#define OFF_BHI  (2 * TILE_B)
#define OFF_BLO  (3 * TILE_B)

__global__ __launch_bounds__(256, 2) void tgemm_k(
    const __nv_bfloat16* __restrict__ Ahi, const __nv_bfloat16* __restrict__ Alo,
    const __nv_bfloat16* __restrict__ Bhi, const __nv_bfloat16* __restrict__ Blo,
    const float* __restrict__ bias, float* __restrict__ C, int Nd, int mode,
    float* __restrict__ Qo, float* __restrict__ Ko, float* __restrict__ Vo)
{
    extern __shared__ char smem[];
    const uint32_t sb = smem_u32(smem);

    const int tid  = threadIdx.x;
    const int lane = tid & 31;
    const int wid  = tid >> 5;
    const int wm   = wid & 1;          // 0..1 : M
    const int wn   = wid >> 1;         // 0..3 : N
    const int g    = lane >> 2;        // 0..7
    const int tg   = lane & 3;         // 0..3

    const int bm = blockIdx.y * 128;
    const int bn = blockIdx.x * 128;

    // ldmatrix per-lane address components
    const int a_row = wm * 64 + (lane & 15);        // + mt*16
    const int a_kc  = (lane >> 4) * 8;              // + ks*16
    const int b_row = wn * 32 + ((lane >> 4) << 3) + (lane & 7);  // + p*16
    const int b_kc  = ((lane >> 3) & 1) * 8;        // + ks*16

    // gmem->smem loader role: 4 tiles x 64 threads, 8 granules (16B) each
    const int tile = tid >> 6;         // 0:Ahi 1:Alo 2:Bhi 3:Blo
    const int lt   = tid & 63;
    const __nv_bfloat16* src_base =
        (tile == 0) ? Ahi : (tile == 1) ? Alo : (tile == 2) ? Bhi : Blo;
    const int rowbase = (tile < 2) ? bm : bn;
    const uint32_t tile_off = tile * TILE_B;

    auto load_chunk = [&](int k0, int stage) {
        const uint32_t dbase = sb + stage * STAGE_B + tile_off;
#pragma unroll
        for (int j = 0; j < 8; j++) {
            int id  = lt + j * 64;          // 0..511
            int row = id >> 2;              // 0..127
            int gr  = id & 3;               // 16B granule within 64B row
            const void* src = src_base + (size_t)(rowbase + row) * Ddim + k0 + gr * 8;
            cp_async16(dbase + (uint32_t)(row * (LDK * 2) + gr * 16), src);
        }
        CP_COMMIT();
    };

    float acc[4][4][4];
#pragma unroll
    for (int i = 0; i < 4; i++)
#pragma unroll
        for (int j = 0; j < 4; j++)
#pragma unroll
            for (int q = 0; q < 4; q++) acc[i][j][q] = 0.f;

    load_chunk(0, 0);

    const int NCH = Ddim / BK;   // 24
    for (int c = 0; c < NCH; c++) {
        cp_wait<0>();
        __syncthreads();
        if (c + 1 < NCH) load_chunk((c + 1) * BK, (c + 1) & 1);

        const uint32_t st = sb + (c & 1) * STAGE_B;

#pragma unroll
        for (int ks = 0; ks < 2; ks++) {
            const int kcA = ks * 16 + a_kc;
            const int kcB = ks * 16 + b_kc;
            uint32_t ah[4][4], al[4][4];
#pragma unroll
            for (int mt = 0; mt < 4; mt++) {
                uint32_t addr = st + (uint32_t)(((a_row + mt * 16) * LDK + kcA) * 2);
                ldsm4(ah[mt][0], ah[mt][1], ah[mt][2], ah[mt][3], addr + OFF_AHI);
                ldsm4(al[mt][0], al[mt][1], al[mt][2], al[mt][3], addr + OFF_ALO);
            }
#pragma unroll
            for (int p = 0; p < 2; p++) {
                uint32_t baddr = st + (uint32_t)(((b_row + p * 16) * LDK + kcB) * 2);
                uint32_t bh[2][2], bl[2][2];
                ldsm4(bh[0][0], bh[0][1], bh[1][0], bh[1][1], baddr + OFF_BHI);
                ldsm4(bl[0][0], bl[0][1], bl[1][0], bl[1][1], baddr + OFF_BLO);
#pragma unroll
                for (int q = 0; q < 2; q++) {
                    const int nt = p * 2 + q;
#pragma unroll
                    for (int mt = 0; mt < 4; mt++) {
                        mma16816(acc[mt][nt], ah[mt][0], ah[mt][1], ah[mt][2], ah[mt][3],
                                 bh[q][0], bh[q][1]);
                        mma16816(acc[mt][nt], ah[mt][0], ah[mt][1], ah[mt][2], ah[mt][3],
                                 bl[q][0], bl[q][1]);
                        mma16816(acc[mt][nt], al[mt][0], al[mt][1], al[mt][2], al[mt][3],
                                 bh[q][0], bh[q][1]);
                    }
                }
            }
        }
    }

    // epilogue
    if (mode == 1) {
#pragma unroll
        for (int mt = 0; mt < 4; mt++) {
            int r0 = bm + wm * 64 + mt * 16 + g;
#pragma unroll
            for (int nt = 0; nt < 4; nt++) {
                int c0 = bn + wn * 32 + nt * 8 + tg * 2;
                float b0 = bias[c0], b1 = bias[c0 + 1];
                float2 v0 = make_float2(acc[mt][nt][0] + b0, acc[mt][nt][1] + b1);
                float2 v1 = make_float2(acc[mt][nt][2] + b0, acc[mt][nt][3] + b1);
                *(float2*)(C + (size_t)r0 * Nd + c0) = v0;
                *(float2*)(C + (size_t)(r0 + 8) * Nd + c0) = v1;
            }
        }
    } else {
        // scatter into q/k/v (B,12,N,64) head layout
#pragma unroll
        for (int nt = 0; nt < 4; nt++) {
            int c0 = bn + wn * 32 + nt * 8 + tg * 2;
            int t = c0 / Ddim;
            int rem = c0 - t * Ddim;
            int h = rem >> 6, d = rem & 63;
            float* dst = (t == 0) ? Qo : (t == 1) ? Ko : Vo;
#pragma unroll
            for (int mt = 0; mt < 4; mt++) {
                int r0 = bm + wm * 64 + mt * 16 + g;
#pragma unroll
                for (int rr = 0; rr < 2; rr++) {
                    int r = r0 + rr * 8;
                    int b = r / Ndim;
                    int n = r - b * Ndim;
                    size_t off = (((size_t)(b * Hh + h)) * Ndim + n) * HD + d;
                    float2 v = make_float2(acc[mt][nt][2 * rr], acc[mt][nt][2 * rr + 1]);
                    *(float2*)(dst + off) = v;
                }
            }
        }
    }
}

// ---------------------------------------------------------------------------
// fp32 -> bf16 hi/lo split
// ---------------------------------------------------------------------------
__global__ void cvt_split_k(const float* __restrict__ in,
                            __nv_bfloat16* __restrict__ hi,
                            __nv_bfloat16* __restrict__ lo, size_t n)
{
    size_t i = (size_t)blockIdx.x * 256 + threadIdx.x;
    if (i >= n) return;
    float v = in[i];
    __nv_bfloat16 h = __float2bfloat16(v);
    hi[i] = h;
    lo[i] = __float2bfloat16(v - __bfloat162float(h));
}

// ---------------------------------------------------------------------------
// Spatial attention: 768 groups of 196 rows (heads 0..5), float4 version.
// 224 threads (196 active = 87.5%). Output written straight into
// g_wf_hi/lo head-interleaved layout with bf16 split.
// ---------------------------------------------------------------------------
#define SPAT_T 224
__global__ __launch_bounds__(SPAT_T) void attn_spatial_k()
{
    __shared__ float4 K4[64][16];
    __shared__ float4 V4[64][16];

    const int g = blockIdx.x;
    const int b = g / 96;
    const int h = (g % 96) / 16;
    const int f = g % 16;
    const size_t base = (((size_t)(b * Hh + h)) * Ndim + f * Pdim) * HD;

    const int tid = threadIdx.x;
    const bool active = tid < Pdim;

    float4 q4[16], a4[16];
    float mx = -1e30f, lsum = 0.f;
    if (active) {
        const float4* qp = (const float4*)(g_q + base + (size_t)tid * HD);
#pragma unroll
        for (int i = 0; i < 16; i++) q4[i] = qp[i];
#pragma unroll
        for (int i = 0; i < 16; i++) a4[i] = make_float4(0.f, 0.f, 0.f, 0.f);
    }

    const float scale = 0.125f;

    for (int j0 = 0; j0 < Pdim; j0 += 64) {
        int cnt = Pdim - j0; if (cnt > 64) cnt = 64;
        __syncthreads();
        {
            const float4* kp = (const float4*)(g_k + base + (size_t)j0 * HD);
            const float4* vp = (const float4*)(g_v + base + (size_t)j0 * HD);
            for (int t = tid; t < cnt * 16; t += SPAT_T) {
                K4[t >> 4][t & 15] = kp[t];
                V4[t >> 4][t & 15] = vp[t];
            }
        }
        __syncthreads();
        if (active) {
            for (int j = 0; j < cnt; j++) {
                float s = 0.f;
#pragma unroll
                for (int i = 0; i < 16; i++) {
                    float4 kv = K4[j][i];
                    s = fmaf(q4[i].x, kv.x, s);
                    s = fmaf(q4[i].y, kv.y, s);
                    s = fmaf(q4[i].z, kv.z, s);
                    s = fmaf(q4[i].w, kv.w, s);
                }
                s *= scale;
                if (s <= mx) {
                    float p = __expf(s - mx);
                    lsum += p;
#pragma unroll
                    for (int i = 0; i < 16; i++) {
                        float4 vv = V4[j][i];
                        a4[i].x = fmaf(p, vv.x, a4[i].x);
                        a4[i].y = fmaf(p, vv.y, a4[i].y);
                        a4[i].z = fmaf(p, vv.z, a4[i].z);
                        a4[i].w = fmaf(p, vv.w, a4[i].w);
                    }
                } else {
                    float corr = __expf(mx - s);
                    lsum = lsum * corr + 1.f;
#pragma unroll
                    for (int i = 0; i < 16; i++) {
                        float4 vv = V4[j][i];
                        a4[i].x = fmaf(a4[i].x, corr, vv.x);
                        a4[i].y = fmaf(a4[i].y, corr, vv.y);
                        a4[i].z = fmaf(a4[i].z, corr, vv.z);
                        a4[i].w = fmaf(a4[i].w, corr, vv.w);
                    }
                    mx = s;
                }
            }
        }
    }

    if (active) {
        float inv = 1.f / lsum;
        const int nglob = f * Pdim + tid;
        const size_t obase = ((size_t)b * Ndim + nglob) * Ddim + h * HD;
#pragma unroll
        for (int i = 0; i < 16; i++) {
            float vals[4] = { a4[i].x * inv, a4[i].y * inv, a4[i].z * inv, a4[i].w * inv };
#pragma unroll
            for (int j = 0; j < 4; j += 2) {
                float v0 = vals[j], v1 = vals[j + 1];
                __nv_bfloat16 h0 = __float2bfloat16(v0);
                __nv_bfloat16 h1 = __float2bfloat16(v1);
                __nv_bfloat162 hv; hv.x = h0; hv.y = h1;
                __nv_bfloat162 lv;
                lv.x = __float2bfloat16(v0 - __bfloat162float(h0));
                lv.y = __float2bfloat16(v1 - __bfloat162float(h1));
                *(__nv_bfloat162*)(g_wf_hi + obase + i * 4 + j) = hv;
                *(__nv_bfloat162*)(g_wf_lo + obase + i * 4 + j) = lv;
            }
        }
    }
}

// ---------------------------------------------------------------------------
// Temporal attention: heads 6..11, groups of 16 rows. Writes g_wf directly.
// ---------------------------------------------------------------------------
__global__ __launch_bounds__(128) void attn_temporal_k()
{
    int tid = blockIdx.x * 128 + threadIdx.x;
    const int TOT = Bdim * 6 * Ndim;
    if (tid >= TOT) return;
    int b = tid / (6 * Ndim);
    int rr = tid - b * (6 * Ndim);
    int h = 6 + rr / Ndim;
    int n = rr % Ndim;
    int n0 = n & ~15;
    size_t row = (((size_t)(b * Hh + h)) * Ndim + n) * HD;
    size_t gb  = (((size_t)(b * Hh + h)) * Ndim + n0) * HD;

    float4 q4[16];
    const float4* qp = (const float4*)(g_q + row);
#pragma unroll
    for (int i = 0; i < 16; i++) q4[i] = qp[i];

    float s[16];
    float mx = -1e30f;
#pragma unroll
    for (int f = 0; f < 16; f++) {
        const float4* kp = (const float4*)(g_k + gb + (size_t)f * HD);
        float a = 0.f;
#pragma unroll
        for (int i = 0; i < 16; i++) {
            float4 kv = kp[i];
            a = fmaf(q4[i].x, kv.x, a);
            a = fmaf(q4[i].y, kv.y, a);
            a = fmaf(q4[i].z, kv.z, a);
            a = fmaf(q4[i].w, kv.w, a);
        }
        s[f] = a * 0.125f;
        mx = fmaxf(mx, s[f]);
    }
    float lsum = 0.f;
#pragma unroll
    for (int f = 0; f < 16; f++) { s[f] = __expf(s[f] - mx); lsum += s[f]; }
    float inv = 1.f / lsum;
#pragma unroll
    for (int f = 0; f < 16; f++) s[f] *= inv;

    const size_t obase = ((size_t)b * Ndim + n) * Ddim + h * HD;
#pragma unroll
    for (int ch = 0; ch < 4; ch++) {
        float4 a4[4];
#pragma unroll
        for (int i = 0; i < 4; i++) a4[i] = make_float4(0.f, 0.f, 0.f, 0.f);
#pragma unroll
        for (int f = 0; f < 16; f++) {
            float p = s[f];
            const float4* vp = (const float4*)(g_v + gb + (size_t)f * HD + ch * 16);
#pragma unroll
            for (int i = 0; i < 4; i++) {
                float4 vv = vp[i];
                a4[i].x = fmaf(p, vv.x, a4[i].x);
                a4[i].y = fmaf(p, vv.y, a4[i].y);
                a4[i].z = fmaf(p, vv.z, a4[i].z);
                a4[i].w = fmaf(p, vv.w, a4[i].w);
            }
        }
#pragma unroll
        for (int i = 0; i < 4; i++) {
            float vals[4] = { a4[i].x, a4[i].y, a4[i].z, a4[i].w };
#pragma unroll
            for (int j = 0; j < 4; j += 2) {
                float v0 = vals[j], v1 = vals[j + 1];
                __nv_bfloat16 h0 = __float2bfloat16(v0);
                __nv_bfloat16 h1 = __float2bfloat16(v1);
                __nv_bfloat162 hv; hv.x = h0; hv.y = h1;
                __nv_bfloat162 lv;
                lv.x = __float2bfloat16(v0 - __bfloat162float(h0));
                lv.y = __float2bfloat16(v1 - __bfloat162float(h1));
                size_t o = obase + ch * 16 + i * 4 + j;
                *(__nv_bfloat162*)(g_wf_hi + o) = hv;
                *(__nv_bfloat162*)(g_wf_lo + o) = lv;
            }
        }
    }
}

// ---------------------------------------------------------------------------
// Launch
// ---------------------------------------------------------------------------
extern "C" void kernel_launch(void* const* d_in, const int* in_sizes, int n_in,
                              void* d_out, int out_size)
{
    const float* x      = (const float*)d_in[0];
    const float* w_qkv  = (const float*)d_in[1];
    const float* w_proj = (const float*)d_in[2];
    const float* b_proj = (const float*)d_in[3];
    float* out = (float*)d_out;

    float *p_q, *p_k, *p_v;
    __nv_bfloat16 *p_xhi, *p_xlo, *p_qkvw_hi, *p_qkvw_lo;
    __nv_bfloat16 *p_projw_hi, *p_projw_lo, *p_wfhi, *p_wflo;
    cudaGetSymbolAddress((void**)&p_q, g_q);
    cudaGetSymbolAddress((void**)&p_k, g_k);
    cudaGetSymbolAddress((void**)&p_v, g_v);
    cudaGetSymbolAddress((void**)&p_xhi, g_xhi);
    cudaGetSymbolAddress((void**)&p_xlo, g_xlo);
    cudaGetSymbolAddress((void**)&p_qkvw_hi, g_wqkv_hi);
    cudaGetSymbolAddress((void**)&p_qkvw_lo, g_wqkv_lo);
    cudaGetSymbolAddress((void**)&p_projw_hi, g_wproj_hi);
    cudaGetSymbolAddress((void**)&p_projw_lo, g_wproj_lo);
    cudaGetSymbolAddress((void**)&p_wfhi, g_wf_hi);
    cudaGetSymbolAddress((void**)&p_wflo, g_wf_lo);

    cudaFuncSetAttribute(tgemm_k, cudaFuncAttributeMaxDynamicSharedMemorySize, GSMEM);

    // 0) bf16 splits of inputs / weights
    cvt_split_k<<<(unsigned)((MD_ELEMS + 255) / 256), 256>>>(x, p_xhi, p_xlo, MD_ELEMS);
    cvt_split_k<<<(unsigned)(((size_t)E3 * Ddim + 255) / 256), 256>>>(
        w_qkv, p_qkvw_hi, p_qkvw_lo, (size_t)E3 * Ddim);
    cvt_split_k<<<(unsigned)(((size_t)Ddim * Ddim + 255) / 256), 256>>>(
        w_proj, p_projw_hi, p_projw_lo, (size_t)Ddim * Ddim);

    // 1) qkv GEMM with fused scatter into q/k/v head layout
    tgemm_k<<<dim3(E3 / 128, Mrows / 128), 256, GSMEM>>>(
        p_xhi, p_xlo, p_qkvw_hi, p_qkvw_lo, nullptr, nullptr, E3, 0,
        p_q, p_k, p_v);

    // 2) spatial attention (writes g_wf_hi/lo directly)
    attn_spatial_k<<<768, SPAT_T>>>();

    // 3) temporal attention (writes g_wf_hi/lo directly)
    attn_temporal_k<<<(Bdim * 6 * Ndim) / 128, 128>>>();

    // 4) out = wf @ w_proj^T + b_proj
    tgemm_k<<<dim3(Ddim / 128, Mrows / 128), 256, GSMEM>>>(
        p_wfhi, p_wflo, p_projw_hi, p_projw_lo, b_proj, out, Ddim, 1,
        nullptr, nullptr, nullptr);
}